// round 1
// baseline (speedup 1.0000x reference)
#include <cuda_runtime.h>
#include <cuda_bf16.h>
#include <cstdint>

// Problem constants
#define BB 256
#define SS 64
#define DD 1024
#define HH 16
#define DH 64
#define NREL 15
#define MTOT (BB*SS)       // 16384

// Scratch (device globals; no allocation allowed)
__device__ float g_q[(size_t)BB*HH*SS*DH];   // (B,H,S,DH)
__device__ float g_k[(size_t)BB*HH*SS*DH];
__device__ float g_v[(size_t)BB*HH*SS*DH];
__device__ float g_ctx[(size_t)MTOT*DD];     // (B,S,D)
__device__ float g_c[SS*SS];                 // rel_q . rel_k table (S,S)

// ---------------------------------------------------------------------------
// prep: c[i][j] = sum_d (eq_h[rr]+eq_w[rc]) * (ek_h[rr]+ek_w[rc])
// ---------------------------------------------------------------------------
__global__ void prep_kernel(const float* __restrict__ eq_h, const float* __restrict__ eq_w,
                            const float* __restrict__ ek_h, const float* __restrict__ ek_w) {
    int idx = blockIdx.x * 256 + threadIdx.x;   // 4096 total
    int i = idx >> 6, j = idx & 63;
    int rr = (i >> 3) - (j >> 3) + 7;
    int rc = (i & 7) - (j & 7) + 7;
    float acc = 0.f;
    #pragma unroll 8
    for (int d = 0; d < 64; ++d) {
        float a = eq_h[rr * 64 + d] + eq_w[rc * 64 + d];
        float b = ek_h[rr * 64 + d] + ek_w[rc * 64 + d];
        acc += a * b;
    }
    g_c[idx] = acc;
}

// ---------------------------------------------------------------------------
// SGEMM mainloop: C[m,n] = sum_k A[m,k] * Bm[n,k]; 128x128 tile, BK=8,
// 256 threads, 8x8 per thread, double-buffered smem.
// ---------------------------------------------------------------------------
__device__ __forceinline__ void gemm_mainloop(
    const float* __restrict__ A, const float* __restrict__ Bm,
    int m0, int n0, int K, float acc[8][8], float* smem)
{
    float (*As)[8][128] = (float (*)[8][128])smem;
    float (*Bs)[8][128] = (float (*)[8][128])(smem + 2 * 8 * 128);

    int tid  = threadIdx.x;
    int lrow = tid >> 1;
    int lk   = (tid & 1) * 4;
    const float* gA = A  + (size_t)(m0 + lrow) * K + lk;
    const float* gB = Bm + (size_t)(n0 + lrow) * K + lk;
    int ty = tid >> 4, tx = tid & 15;

    // tile 0
    {
        float4 a0 = *(const float4*)gA;
        float4 b0 = *(const float4*)gB;
        As[0][lk+0][lrow]=a0.x; As[0][lk+1][lrow]=a0.y; As[0][lk+2][lrow]=a0.z; As[0][lk+3][lrow]=a0.w;
        Bs[0][lk+0][lrow]=b0.x; Bs[0][lk+1][lrow]=b0.y; Bs[0][lk+2][lrow]=b0.z; Bs[0][lk+3][lrow]=b0.w;
    }
    __syncthreads();

    int nk = K >> 3;
    for (int kt = 0; kt < nk; ++kt) {
        int buf = kt & 1;
        float4 pa, pb;
        bool more = (kt + 1 < nk);
        if (more) {
            pa = *(const float4*)(gA + (kt + 1) * 8);
            pb = *(const float4*)(gB + (kt + 1) * 8);
        }
        #pragma unroll
        for (int kk = 0; kk < 8; ++kk) {
            float a[8], b[8];
            *(float4*)&a[0] = *(float4*)&As[buf][kk][ty * 8];
            *(float4*)&a[4] = *(float4*)&As[buf][kk][ty * 8 + 4];
            *(float4*)&b[0] = *(float4*)&Bs[buf][kk][tx * 8];
            *(float4*)&b[4] = *(float4*)&Bs[buf][kk][tx * 8 + 4];
            #pragma unroll
            for (int ii = 0; ii < 8; ++ii)
                #pragma unroll
                for (int jj = 0; jj < 8; ++jj)
                    acc[ii][jj] = fmaf(a[ii], b[jj], acc[ii][jj]);
        }
        if (more) {
            int nb = buf ^ 1;
            As[nb][lk+0][lrow]=pa.x; As[nb][lk+1][lrow]=pa.y; As[nb][lk+2][lrow]=pa.z; As[nb][lk+3][lrow]=pa.w;
            Bs[nb][lk+0][lrow]=pb.x; Bs[nb][lk+1][lrow]=pb.y; Bs[nb][lk+2][lrow]=pb.z; Bs[nb][lk+3][lrow]=pb.w;
            __syncthreads();
        }
    }
}

// QKV projection: out scattered into (B,H,S,DH) layout
__global__ __launch_bounds__(256) void qkv_gemm_kernel(
    const float* __restrict__ x, const float* __restrict__ wq,
    const float* __restrict__ wk, const float* __restrict__ wv)
{
    __shared__ float smem[2 * 8 * 128 * 2];
    int m0 = blockIdx.x * 128;
    int which = blockIdx.y >> 3;
    int n0 = (blockIdx.y & 7) * 128;
    const float* W = (which == 0) ? wq : (which == 1) ? wk : wv;
    float acc[8][8];
    #pragma unroll
    for (int i = 0; i < 8; ++i)
        #pragma unroll
        for (int j = 0; j < 8; ++j) acc[i][j] = 0.f;

    gemm_mainloop(x, W, m0, n0, DD, acc, smem);

    float* dst = (which == 0) ? g_q : (which == 1) ? g_k : g_v;
    int ty = threadIdx.x >> 4, tx = threadIdx.x & 15;
    #pragma unroll
    for (int ii = 0; ii < 8; ++ii) {
        int m = m0 + ty * 8 + ii;
        int b = m >> 6, s = m & 63;
        #pragma unroll
        for (int jj = 0; jj < 8; jj += 4) {
            int n = n0 + tx * 8 + jj;
            int h = n >> 6, d = n & 63;
            float4 v4 = make_float4(acc[ii][jj], acc[ii][jj+1], acc[ii][jj+2], acc[ii][jj+3]);
            *(float4*)&dst[(((size_t)(b * HH + h) * SS + s) << 6) + d] = v4;
        }
    }
}

// Output projection: out = ctx @ wo.T + bo
__global__ __launch_bounds__(256) void out_gemm_kernel(
    const float* __restrict__ wo, const float* __restrict__ bo, float* __restrict__ out)
{
    __shared__ float smem[2 * 8 * 128 * 2];
    int m0 = blockIdx.x * 128;
    int n0 = blockIdx.y * 128;
    float acc[8][8];
    #pragma unroll
    for (int i = 0; i < 8; ++i)
        #pragma unroll
        for (int j = 0; j < 8; ++j) acc[i][j] = 0.f;

    gemm_mainloop(g_ctx, wo, m0, n0, DD, acc, smem);

    int ty = threadIdx.x >> 4, tx = threadIdx.x & 15;
    #pragma unroll
    for (int ii = 0; ii < 8; ++ii) {
        int m = m0 + ty * 8 + ii;
        #pragma unroll
        for (int jj = 0; jj < 8; jj += 4) {
            int n = n0 + tx * 8 + jj;
            float4 v4 = make_float4(acc[ii][jj]   + bo[n],
                                    acc[ii][jj+1] + bo[n+1],
                                    acc[ii][jj+2] + bo[n+2],
                                    acc[ii][jj+3] + bo[n+3]);
            *(float4*)&out[(size_t)m * DD + n] = v4;
        }
    }
}

// ---------------------------------------------------------------------------
// Attention: one block per (b,h). Everything in smem.
// ---------------------------------------------------------------------------
#define LDQ 68                         // padded row stride for q/k/v tiles
#define LDE 65                         // padded row stride for rel tables
#define ATT_SMEM_FLOATS (3*64*LDQ + 4096 + 6*NREL*LDE + 6*1024)
#define ATT_SMEM_BYTES  (ATT_SMEM_FLOATS * 4)

__global__ __launch_bounds__(256) void attn_kernel(
    const float* __restrict__ eq_h, const float* __restrict__ eq_w,
    const float* __restrict__ ek_h, const float* __restrict__ ek_w,
    const float* __restrict__ ev_h, const float* __restrict__ ev_w)
{
    extern __shared__ float sm[];
    float* qs    = sm;                    // 64*LDQ
    float* ks    = qs + 64 * LDQ;
    float* vs    = ks + 64 * LDQ;
    float* sc    = vs + 64 * LDQ;         // 64*64 scores/attn
    float* t_ekh = sc + 4096;             // NREL*LDE each
    float* t_ekw = t_ekh + NREL * LDE;
    float* t_eqh = t_ekw + NREL * LDE;
    float* t_eqw = t_eqh + NREL * LDE;
    float* t_evh = t_eqw + NREL * LDE;
    float* t_evw = t_evh + NREL * LDE;
    float* Ah    = t_evw + NREL * LDE;    // 64*16 each
    float* Aw    = Ah + 1024;
    float* Ch    = Aw + 1024;
    float* Cw    = Ch + 1024;
    float* Wh    = Cw + 1024;
    float* Ww    = Wh + 1024;

    int tid = threadIdx.x;
    int bx  = blockIdx.x;                 // b*H + h
    size_t base = (size_t)bx * (SS * DH);

    // Load q/k/v tiles (coalesced), rel tables
    #pragma unroll
    for (int it = 0; it < 4; ++it) {
        int e = tid * 4 + it * 1024;
        int s = e >> 6, d = e & 63;
        *(float4*)&qs[s * LDQ + d] = *(const float4*)&g_q[base + e];
        *(float4*)&ks[s * LDQ + d] = *(const float4*)&g_k[base + e];
        *(float4*)&vs[s * LDQ + d] = *(const float4*)&g_v[base + e];
    }
    for (int idx = tid; idx < NREL * 64; idx += 256) {
        int r = idx >> 6, d = idx & 63;
        int o = r * LDE + d;
        t_ekh[o] = ek_h[idx]; t_ekw[o] = ek_w[idx];
        t_eqh[o] = eq_h[idx]; t_eqw[o] = eq_w[idx];
        t_evh[o] = ev_h[idx]; t_evw[o] = ev_w[idx];
    }
    __syncthreads();

    // A/C tables: Ah[i,r]=q_i.ek_h[r], Aw[i,r]=q_i.ek_w[r], Ch[j,r]=eq_h[r].k_j, Cw similar
    {
        int r = tid & 15, i0 = tid >> 4;
        if (r < NREL) {
            for (int i = i0; i < 64; i += 16) {
                const float* qrow = qs + i * LDQ;
                const float* krow = ks + i * LDQ;
                const float* ekh = t_ekh + r * LDE; const float* ekw = t_ekw + r * LDE;
                const float* eqh = t_eqh + r * LDE; const float* eqw = t_eqw + r * LDE;
                float ah = 0.f, aw = 0.f, ch = 0.f, cw = 0.f;
                #pragma unroll 8
                for (int d = 0; d < 64; ++d) {
                    float qv = qrow[d], kv = krow[d];
                    ah = fmaf(qv, ekh[d], ah);
                    aw = fmaf(qv, ekw[d], aw);
                    ch = fmaf(kv, eqh[d], ch);
                    cw = fmaf(kv, eqw[d], cw);
                }
                Ah[i * 16 + r] = ah; Aw[i * 16 + r] = aw;
                Ch[i * 16 + r] = ch; Cw[i * 16 + r] = cw;
            }
        }
    }
    __syncthreads();

    // Scores: 4x4 per thread
    {
        int ti = tid >> 4, tj = tid & 15;
        float accv[4][4];
        #pragma unroll
        for (int a = 0; a < 4; ++a)
            #pragma unroll
            for (int b = 0; b < 4; ++b) accv[a][b] = 0.f;
        const float* qa = qs + (ti * 4) * LDQ;
        const float* kb = ks + (tj * 4) * LDQ;
        #pragma unroll 4
        for (int d = 0; d < 64; ++d) {
            float a0 = qa[d], a1 = qa[LDQ + d], a2 = qa[2 * LDQ + d], a3 = qa[3 * LDQ + d];
            float b0 = kb[d], b1 = kb[LDQ + d], b2 = kb[2 * LDQ + d], b3 = kb[3 * LDQ + d];
            accv[0][0] = fmaf(a0, b0, accv[0][0]); accv[0][1] = fmaf(a0, b1, accv[0][1]);
            accv[0][2] = fmaf(a0, b2, accv[0][2]); accv[0][3] = fmaf(a0, b3, accv[0][3]);
            accv[1][0] = fmaf(a1, b0, accv[1][0]); accv[1][1] = fmaf(a1, b1, accv[1][1]);
            accv[1][2] = fmaf(a1, b2, accv[1][2]); accv[1][3] = fmaf(a1, b3, accv[1][3]);
            accv[2][0] = fmaf(a2, b0, accv[2][0]); accv[2][1] = fmaf(a2, b1, accv[2][1]);
            accv[2][2] = fmaf(a2, b2, accv[2][2]); accv[2][3] = fmaf(a2, b3, accv[2][3]);
            accv[3][0] = fmaf(a3, b0, accv[3][0]); accv[3][1] = fmaf(a3, b1, accv[3][1]);
            accv[3][2] = fmaf(a3, b2, accv[3][2]); accv[3][3] = fmaf(a3, b3, accv[3][3]);
        }
        #pragma unroll
        for (int ii = 0; ii < 4; ++ii)
            #pragma unroll
            for (int jj = 0; jj < 4; ++jj) {
                int i = ti * 4 + ii, j = tj * 4 + jj;
                int rr = (i >> 3) - (j >> 3) + 7;
                int rc = (i & 7) - (j & 7) + 7;
                float sv = accv[ii][jj] + Ah[i * 16 + rr] + Aw[i * 16 + rc]
                         + Ch[j * 16 + rr] + Cw[j * 16 + rc] + __ldg(&g_c[i * 64 + j]);
                sc[i * 64 + j] = sv * 0.125f;   // 1/sqrt(DH)
            }
    }
    __syncthreads();

    // Softmax per row
    {
        int wid = tid >> 5, lane = tid & 31;
        for (int row = wid; row < 64; row += 8) {
            float* srow = sc + row * 64;
            float x0 = srow[lane], x1 = srow[lane + 32];
            float m = fmaxf(x0, x1);
            #pragma unroll
            for (int o = 16; o > 0; o >>= 1) m = fmaxf(m, __shfl_xor_sync(0xffffffffu, m, o));
            float e0 = __expf(x0 - m), e1 = __expf(x1 - m);
            float ssum = e0 + e1;
            #pragma unroll
            for (int o = 16; o > 0; o >>= 1) ssum += __shfl_xor_sync(0xffffffffu, ssum, o);
            float inv = 1.0f / ssum;
            srow[lane] = e0 * inv; srow[lane + 32] = e1 * inv;
        }
    }
    __syncthreads();

    // Wh[i,r] = sum_{j: rr_ij==r} attn[i,j]; Ww over columns
    {
        int r = tid & 15, i0 = tid >> 4;
        if (r < NREL) {
            for (int i = i0; i < 64; i += 16) {
                int rowi = i >> 3, coli = i & 7;
                int rowj = rowi - (r - 7);
                float wh = 0.f;
                if (rowj >= 0 && rowj < 8) {
                    const float* p = sc + i * 64 + rowj * 8;
                    #pragma unroll
                    for (int c = 0; c < 8; ++c) wh += p[c];
                }
                int colj = coli - (r - 7);
                float ww = 0.f;
                if (colj >= 0 && colj < 8) {
                    const float* p = sc + i * 64 + colj;
                    #pragma unroll
                    for (int rj = 0; rj < 8; ++rj) ww += p[rj * 8];
                }
                Wh[i * 16 + r] = wh; Ww[i * 16 + r] = ww;
            }
        }
    }
    __syncthreads();

    // ctx = attn @ v + Wh @ ev_h + Ww @ ev_w ; write (B,S,D)
    {
        int i  = tid >> 2;
        int d0 = (tid & 3) * 16;
        float c16[16];
        #pragma unroll
        for (int dd = 0; dd < 16; ++dd) c16[dd] = 0.f;
        const float* srow = sc + i * 64;
        for (int j = 0; j < 64; ++j) {
            float a = srow[j];
            const float* vr = vs + j * LDQ + d0;
            #pragma unroll
            for (int dd = 0; dd < 16; ++dd) c16[dd] = fmaf(a, vr[dd], c16[dd]);
        }
        #pragma unroll
        for (int r = 0; r < NREL; ++r) {
            float wh = Wh[i * 16 + r], ww = Ww[i * 16 + r];
            const float* eh = t_evh + r * LDE + d0;
            const float* ew = t_evw + r * LDE + d0;
            #pragma unroll
            for (int dd = 0; dd < 16; ++dd)
                c16[dd] = fmaf(wh, eh[dd], fmaf(ww, ew[dd], c16[dd]));
        }
        int b = bx >> 4, h = bx & 15;
        float* dst = g_ctx + (size_t)(b * SS + i) * DD + h * DH + d0;
        #pragma unroll
        for (int dd = 0; dd < 16; dd += 4)
            *(float4*)&dst[dd] = make_float4(c16[dd], c16[dd+1], c16[dd+2], c16[dd+3]);
    }
}

// ---------------------------------------------------------------------------
extern "C" void kernel_launch(void* const* d_in, const int* in_sizes, int n_in,
                              void* d_out, int out_size) {
    const float* x    = (const float*)d_in[0];
    const float* wq   = (const float*)d_in[1];
    const float* wk   = (const float*)d_in[2];
    const float* wv   = (const float*)d_in[3];
    const float* wo   = (const float*)d_in[4];
    const float* bo   = (const float*)d_in[5];
    const float* eq_h = (const float*)d_in[6];
    const float* eq_w = (const float*)d_in[7];
    const float* ek_h = (const float*)d_in[8];
    const float* ek_w = (const float*)d_in[9];
    const float* ev_h = (const float*)d_in[10];
    const float* ev_w = (const float*)d_in[11];
    float* out = (float*)d_out;

    cudaFuncSetAttribute(attn_kernel, cudaFuncAttributeMaxDynamicSharedMemorySize, ATT_SMEM_BYTES);

    prep_kernel<<<16, 256>>>(eq_h, eq_w, ek_h, ek_w);
    qkv_gemm_kernel<<<dim3(128, 24), 256>>>(x, wq, wk, wv);
    attn_kernel<<<BB * HH, 256, ATT_SMEM_BYTES>>>(eq_h, eq_w, ek_h, ek_w, ev_h, ev_w);
    out_gemm_kernel<<<dim3(128, 8), 256>>>(wo, bo, out);
}

// round 3
// speedup vs baseline: 1.9190x; 1.9190x over previous
#include <cuda_runtime.h>
#include <cuda_bf16.h>
#include <cstdint>

// Problem constants
#define BB 256
#define SS 64
#define DD 1024
#define HH 16
#define DH 64
#define NREL 15
#define MTOT (BB*SS)   // 16384

// ---------------------------------------------------------------------------
// Device scratch
// ---------------------------------------------------------------------------
__device__ __align__(1024) float g_q[(size_t)BB*HH*SS*DH];
__device__ __align__(1024) float g_k[(size_t)BB*HH*SS*DH];
__device__ __align__(1024) float g_v[(size_t)BB*HH*SS*DH];
__device__ __align__(1024) float g_ctx[(size_t)MTOT*DD];
__device__ float g_c[SS*SS];

// split-bf16 row-major buffers
__device__ __align__(1024) __nv_bfloat16 g_ah[(size_t)MTOT*DD];     // activations hi
__device__ __align__(1024) __nv_bfloat16 g_al[(size_t)MTOT*DD];     // activations lo
__device__ __align__(1024) __nv_bfloat16 g_wh[(size_t)4*DD*DD];     // weights hi (wq,wk,wv,wo)
__device__ __align__(1024) __nv_bfloat16 g_wl[(size_t)4*DD*DD];     // weights lo

// ---------------------------------------------------------------------------
// PTX helpers (arch-baseline only: sm_80/75 features)
// ---------------------------------------------------------------------------
__device__ __forceinline__ uint32_t smem_u32(const void* p) {
    uint32_t a;
    asm("{ .reg .u64 t; cvta.to.shared.u64 t, %1; cvt.u32.u64 %0, t; }" : "=r"(a) : "l"(p));
    return a;
}
__device__ __forceinline__ void cp16(uint32_t dst, const void* src) {
    asm volatile("cp.async.cg.shared.global [%0], [%1], 16;" :: "r"(dst), "l"(src));
}
__device__ __forceinline__ void cp_commit() {
    asm volatile("cp.async.commit_group;" ::: "memory");
}
template<int N> __device__ __forceinline__ void cp_wait() {
    asm volatile("cp.async.wait_group %0;" :: "n"(N) : "memory");
}
__device__ __forceinline__ void ldsm4(uint32_t (&r)[4], uint32_t a) {
    asm volatile("ldmatrix.sync.aligned.m8n8.x4.shared.b16 {%0,%1,%2,%3}, [%4];"
                 : "=r"(r[0]), "=r"(r[1]), "=r"(r[2]), "=r"(r[3]) : "r"(a));
}
__device__ __forceinline__ void mma16816(float (&c)[4], const uint32_t (&a)[4],
                                         uint32_t b0, uint32_t b1) {
    asm volatile("mma.sync.aligned.m16n8k16.row.col.f32.bf16.bf16.f32 "
                 "{%0,%1,%2,%3}, {%4,%5,%6,%7}, {%8,%9}, {%0,%1,%2,%3};"
                 : "+f"(c[0]), "+f"(c[1]), "+f"(c[2]), "+f"(c[3])
                 : "r"(a[0]), "r"(a[1]), "r"(a[2]), "r"(a[3]), "r"(b0), "r"(b1));
}

// ---------------------------------------------------------------------------
// prep: c[i][j] = (eq_h[rr]+eq_w[rc]) . (ek_h[rr]+ek_w[rc])
// ---------------------------------------------------------------------------
__global__ void prep_kernel(const float* __restrict__ eq_h, const float* __restrict__ eq_w,
                            const float* __restrict__ ek_h, const float* __restrict__ ek_w) {
    int idx = blockIdx.x * 256 + threadIdx.x;
    int i = idx >> 6, j = idx & 63;
    int rr = (i >> 3) - (j >> 3) + 7;
    int rc = (i & 7) - (j & 7) + 7;
    float acc = 0.f;
    #pragma unroll 8
    for (int d = 0; d < 64; ++d) {
        float a = eq_h[rr * 64 + d] + eq_w[rc * 64 + d];
        float b = ek_h[rr * 64 + d] + ek_w[rc * 64 + d];
        acc += a * b;
    }
    g_c[idx] = acc;
}

// ---------------------------------------------------------------------------
// fp32 -> split bf16 (hi + lo), row-major. One thread = 8 elems.
// ---------------------------------------------------------------------------
__global__ __launch_bounds__(256) void conv_split_kernel(
    const float* __restrict__ src, __nv_bfloat16* __restrict__ hi, __nv_bfloat16* __restrict__ lo) {
    size_t base = ((size_t)blockIdx.x * 256 + threadIdx.x) * 8;
    float4 a = *(const float4*)(src + base);
    float4 b = *(const float4*)(src + base + 4);
    float v[8] = {a.x, a.y, a.z, a.w, b.x, b.y, b.z, b.w};
    __nv_bfloat16 h[8], l[8];
    #pragma unroll
    for (int i = 0; i < 8; ++i) {
        h[i] = __float2bfloat16(v[i]);
        l[i] = __float2bfloat16(v[i] - __bfloat162float(h[i]));
    }
    *(uint4*)(hi + base) = *(uint4*)h;
    *(uint4*)(lo + base) = *(uint4*)l;
}

// ---------------------------------------------------------------------------
// HMMA split-bf16 GEMM core: acc(128x128) = A(128 x 1024) * B(128 x 1024)^T
// 3 terms: Ah*Bh + Ah*Bl + Al*Bh, fp32 accum.
// Smem stage (32KB): Ah @0, Al @8192, Bh @16384, Bl @24576; each part
// 128 rows x 64B, 16B-chunk col swizzled by ((k8 ^ (row>>1)) & 3).
// ---------------------------------------------------------------------------
#define STAGES 3
#define STAGE_BYTES 32768
#define GEMM_SMEM (STAGES * STAGE_BYTES)

__device__ __forceinline__ void gemm_acc(
    const __nv_bfloat16* __restrict__ Ahp, const __nv_bfloat16* __restrict__ Alp,
    const __nv_bfloat16* __restrict__ Bhp, const __nv_bfloat16* __restrict__ Blp,
    int mbase, int nbase, float acc[4][4][4])
{
    extern __shared__ unsigned char sm_raw[];
    uint32_t smbase = smem_u32(sm_raw);
    int tid = threadIdx.x, lane = tid & 31, wid = tid >> 5;
    int wm = (wid >> 2) * 64, wn = (wid & 3) * 32;

    #pragma unroll
    for (int i = 0; i < 4; ++i)
        #pragma unroll
        for (int j = 0; j < 4; ++j)
            #pragma unroll
            for (int e = 0; e < 4; ++e) acc[i][j][e] = 0.f;

    const __nv_bfloat16* srcA_h = Ahp + (size_t)mbase * DD;
    const __nv_bfloat16* srcA_l = Alp + (size_t)mbase * DD;
    const __nv_bfloat16* srcB_h = Bhp + (size_t)nbase * DD;
    const __nv_bfloat16* srcB_l = Blp + (size_t)nbase * DD;

    int lm  = tid >> 2;            // 0..63  (row for rep 0)
    int lk8 = tid & 3;             // 16B chunk
    uint32_t loff0 = (uint32_t)(lm * 64 + ((lk8 ^ (lm >> 1)) & 3) * 16);
    int lm1 = lm + 64;
    uint32_t loff1 = (uint32_t)(lm1 * 64 + ((lk8 ^ (lm1 >> 1)) & 3) * 16);

    #define LOAD_CHUNK(kc, st) do {                                            \
        uint32_t sb_ = smbase + (st) * STAGE_BYTES;                            \
        size_t g0_ = (size_t)lm  * DD + (kc) * 32 + lk8 * 8;                   \
        size_t g1_ = (size_t)lm1 * DD + (kc) * 32 + lk8 * 8;                   \
        cp16(sb_ + loff0,         srcA_h + g0_);                               \
        cp16(sb_ + loff1,         srcA_h + g1_);                               \
        cp16(sb_ + 8192 + loff0,  srcA_l + g0_);                               \
        cp16(sb_ + 8192 + loff1,  srcA_l + g1_);                               \
        cp16(sb_ + 16384 + loff0, srcB_h + g0_);                               \
        cp16(sb_ + 16384 + loff1, srcB_h + g1_);                               \
        cp16(sb_ + 24576 + loff0, srcB_l + g0_);                               \
        cp16(sb_ + 24576 + loff1, srcB_l + g1_);                               \
        cp_commit();                                                           \
    } while (0)

    LOAD_CHUNK(0, 0);
    LOAD_CHUNK(1, 1);

    int arow = wm + (lane & 7) + ((lane >> 3) & 1) * 8;
    int brow = wn + (lane & 7) + ((lane >> 3) & 1) * 8;
    int k8l  = (lane >> 4);   // 0 or 1; actual k8 = 2*s16 + k8l

    for (int kc = 0; kc < 32; ++kc) {
        cp_wait<1>();
        __syncthreads();
        if (kc + 2 < 32) {
            int st2 = (kc + 2) % STAGES;
            LOAD_CHUNK(kc + 2, st2);
        } else {
            cp_commit();
        }
        uint32_t sb = smbase + (kc % STAGES) * STAGE_BYTES;

        #pragma unroll
        for (int s16 = 0; s16 < 2; ++s16) {
            int k8 = 2 * s16 + k8l;
            uint32_t ah[4][4], al[4][4];
            #pragma unroll
            for (int i = 0; i < 4; ++i) {
                int r = arow + i * 16;
                uint32_t ad = sb + (uint32_t)(r * 64 + ((k8 ^ (r >> 1)) & 3) * 16);
                ldsm4(ah[i], ad);
                ldsm4(al[i], ad + 8192);
            }
            uint32_t bh[2][4], bl[2][4];
            #pragma unroll
            for (int jp = 0; jp < 2; ++jp) {
                int r = brow + jp * 16;
                uint32_t ad = sb + 16384 + (uint32_t)(r * 64 + ((k8 ^ (r >> 1)) & 3) * 16);
                ldsm4(bh[jp], ad);
                ldsm4(bl[jp], ad + 8192);
            }
            #pragma unroll
            for (int i = 0; i < 4; ++i)
                #pragma unroll
                for (int j = 0; j < 4; ++j) {
                    uint32_t bh0 = bh[j >> 1][j & 1], bh1 = bh[j >> 1][(j & 1) + 2];
                    uint32_t bl0 = bl[j >> 1][j & 1], bl1 = bl[j >> 1][(j & 1) + 2];
                    mma16816(acc[i][j], ah[i], bh0, bh1);
                    mma16816(acc[i][j], ah[i], bl0, bl1);
                    mma16816(acc[i][j], al[i], bh0, bh1);
                }
        }
    }
    #undef LOAD_CHUNK
}

// ---------------------------------------------------------------------------
// QKV GEMM: grid (24, 128). nt>>3 selects q/k/v, (nt&7)*128 = n0.
// ---------------------------------------------------------------------------
__global__ __launch_bounds__(256, 1) void qkv_hmma(const float* dummy) {
    int nt = blockIdx.x, mt = blockIdx.y;
    int which = nt >> 3, nq = nt & 7;
    float acc[4][4][4];
    gemm_acc(g_ah, g_al, g_wh + (size_t)which * DD * DD, g_wl + (size_t)which * DD * DD,
             mt * 128, nq * 128, acc);

    float* dst = (which == 0) ? g_q : (which == 1) ? g_k : g_v;
    int lane = threadIdx.x & 31, wid = threadIdx.x >> 5;
    int wm = (wid >> 2) * 64, wn = (wid & 3) * 32;
    int l4 = lane >> 2, l2 = (lane & 3) * 2;

    #pragma unroll
    for (int i = 0; i < 4; ++i)
        #pragma unroll
        for (int j = 0; j < 4; ++j) {
            int m = mt * 128 + wm + i * 16 + l4;
            int n = nq * 128 + wn + j * 8 + l2;
            int h = n >> 6, d = n & 63;
            int b = m >> 6, s = m & 63;
            *(float2*)&dst[(((size_t)(b * HH + h) * SS + s) << 6) + d] =
                make_float2(acc[i][j][0], acc[i][j][1]);
            *(float2*)&dst[(((size_t)(b * HH + h) * SS + (s + 8)) << 6) + d] =
                make_float2(acc[i][j][2], acc[i][j][3]);
        }
}

// ---------------------------------------------------------------------------
// Output GEMM: grid (8, 128). out = ctx @ wo^T + bo
// ---------------------------------------------------------------------------
__global__ __launch_bounds__(256, 1) void out_hmma(const float* __restrict__ bo,
                                                   float* __restrict__ out) {
    int nt = blockIdx.x, mt = blockIdx.y;
    float acc[4][4][4];
    gemm_acc(g_ah, g_al, g_wh + (size_t)3 * DD * DD, g_wl + (size_t)3 * DD * DD,
             mt * 128, nt * 128, acc);

    int lane = threadIdx.x & 31, wid = threadIdx.x >> 5;
    int wm = (wid >> 2) * 64, wn = (wid & 3) * 32;
    int l4 = lane >> 2, l2 = (lane & 3) * 2;

    #pragma unroll
    for (int i = 0; i < 4; ++i)
        #pragma unroll
        for (int j = 0; j < 4; ++j) {
            int m = mt * 128 + wm + i * 16 + l4;
            int n = nt * 128 + wn + j * 8 + l2;
            float b0 = __ldg(bo + n), b1 = __ldg(bo + n + 1);
            *(float2*)&out[(size_t)m * DD + n] =
                make_float2(acc[i][j][0] + b0, acc[i][j][1] + b1);
            *(float2*)&out[(size_t)(m + 8) * DD + n] =
                make_float2(acc[i][j][2] + b0, acc[i][j][3] + b1);
        }
}

// ---------------------------------------------------------------------------
// Attention: one block per (b,h). Validated round-1 version.
// ---------------------------------------------------------------------------
#define LDQ 68
#define LDE 65
#define ATT_SMEM_FLOATS (3*64*LDQ + 4096 + 6*NREL*LDE + 6*1024)
#define ATT_SMEM_BYTES  (ATT_SMEM_FLOATS * 4)

__global__ __launch_bounds__(256) void attn_kernel(
    const float* __restrict__ eq_h, const float* __restrict__ eq_w,
    const float* __restrict__ ek_h, const float* __restrict__ ek_w,
    const float* __restrict__ ev_h, const float* __restrict__ ev_w)
{
    extern __shared__ float sm[];
    float* qs    = sm;
    float* ks    = qs + 64 * LDQ;
    float* vs    = ks + 64 * LDQ;
    float* sc    = vs + 64 * LDQ;
    float* t_ekh = sc + 4096;
    float* t_ekw = t_ekh + NREL * LDE;
    float* t_eqh = t_ekw + NREL * LDE;
    float* t_eqw = t_eqh + NREL * LDE;
    float* t_evh = t_eqw + NREL * LDE;
    float* t_evw = t_evh + NREL * LDE;
    float* Ah    = t_evw + NREL * LDE;
    float* Aw    = Ah + 1024;
    float* Ch    = Aw + 1024;
    float* Cw    = Ch + 1024;
    float* Wh    = Cw + 1024;
    float* Ww    = Wh + 1024;

    int tid = threadIdx.x;
    int bx  = blockIdx.x;
    size_t base = (size_t)bx * (SS * DH);

    #pragma unroll
    for (int it = 0; it < 4; ++it) {
        int e = tid * 4 + it * 1024;
        int s = e >> 6, d = e & 63;
        *(float4*)&qs[s * LDQ + d] = *(const float4*)&g_q[base + e];
        *(float4*)&ks[s * LDQ + d] = *(const float4*)&g_k[base + e];
        *(float4*)&vs[s * LDQ + d] = *(const float4*)&g_v[base + e];
    }
    for (int idx = tid; idx < NREL * 64; idx += 256) {
        int r = idx >> 6, d = idx & 63;
        int o = r * LDE + d;
        t_ekh[o] = ek_h[idx]; t_ekw[o] = ek_w[idx];
        t_eqh[o] = eq_h[idx]; t_eqw[o] = eq_w[idx];
        t_evh[o] = ev_h[idx]; t_evw[o] = ev_w[idx];
    }
    __syncthreads();

    {
        int r = tid & 15, i0 = tid >> 4;
        if (r < NREL) {
            for (int i = i0; i < 64; i += 16) {
                const float* qrow = qs + i * LDQ;
                const float* krow = ks + i * LDQ;
                const float* ekh = t_ekh + r * LDE; const float* ekw = t_ekw + r * LDE;
                const float* eqh = t_eqh + r * LDE; const float* eqw = t_eqw + r * LDE;
                float ah = 0.f, aw = 0.f, ch = 0.f, cw = 0.f;
                #pragma unroll 8
                for (int d = 0; d < 64; ++d) {
                    float qv = qrow[d], kv = krow[d];
                    ah = fmaf(qv, ekh[d], ah);
                    aw = fmaf(qv, ekw[d], aw);
                    ch = fmaf(kv, eqh[d], ch);
                    cw = fmaf(kv, eqw[d], cw);
                }
                Ah[i * 16 + r] = ah; Aw[i * 16 + r] = aw;
                Ch[i * 16 + r] = ch; Cw[i * 16 + r] = cw;
            }
        }
    }
    __syncthreads();

    {
        int ti = tid >> 4, tj = tid & 15;
        float accv[4][4];
        #pragma unroll
        for (int a = 0; a < 4; ++a)
            #pragma unroll
            for (int b = 0; b < 4; ++b) accv[a][b] = 0.f;
        const float* qa = qs + (ti * 4) * LDQ;
        const float* kb = ks + (tj * 4) * LDQ;
        #pragma unroll 4
        for (int d = 0; d < 64; ++d) {
            float a0 = qa[d], a1 = qa[LDQ + d], a2 = qa[2 * LDQ + d], a3 = qa[3 * LDQ + d];
            float b0 = kb[d], b1 = kb[LDQ + d], b2 = kb[2 * LDQ + d], b3 = kb[3 * LDQ + d];
            accv[0][0] = fmaf(a0, b0, accv[0][0]); accv[0][1] = fmaf(a0, b1, accv[0][1]);
            accv[0][2] = fmaf(a0, b2, accv[0][2]); accv[0][3] = fmaf(a0, b3, accv[0][3]);
            accv[1][0] = fmaf(a1, b0, accv[1][0]); accv[1][1] = fmaf(a1, b1, accv[1][1]);
            accv[1][2] = fmaf(a1, b2, accv[1][2]); accv[1][3] = fmaf(a1, b3, accv[1][3]);
            accv[2][0] = fmaf(a2, b0, accv[2][0]); accv[2][1] = fmaf(a2, b1, accv[2][1]);
            accv[2][2] = fmaf(a2, b2, accv[2][2]); accv[2][3] = fmaf(a2, b3, accv[2][3]);
            accv[3][0] = fmaf(a3, b0, accv[3][0]); accv[3][1] = fmaf(a3, b1, accv[3][1]);
            accv[3][2] = fmaf(a3, b2, accv[3][2]); accv[3][3] = fmaf(a3, b3, accv[3][3]);
        }
        #pragma unroll
        for (int ii = 0; ii < 4; ++ii)
            #pragma unroll
            for (int jj = 0; jj < 4; ++jj) {
                int i = ti * 4 + ii, j = tj * 4 + jj;
                int rr = (i >> 3) - (j >> 3) + 7;
                int rc = (i & 7) - (j & 7) + 7;
                float sv = accv[ii][jj] + Ah[i * 16 + rr] + Aw[i * 16 + rc]
                         + Ch[j * 16 + rr] + Cw[j * 16 + rc] + __ldg(&g_c[i * 64 + j]);
                sc[i * 64 + j] = sv * 0.125f;
            }
    }
    __syncthreads();

    {
        int wid = tid >> 5, lane = tid & 31;
        for (int row = wid; row < 64; row += 8) {
            float* srow = sc + row * 64;
            float x0 = srow[lane], x1 = srow[lane + 32];
            float m = fmaxf(x0, x1);
            #pragma unroll
            for (int o = 16; o > 0; o >>= 1) m = fmaxf(m, __shfl_xor_sync(0xffffffffu, m, o));
            float e0 = __expf(x0 - m), e1 = __expf(x1 - m);
            float ssum = e0 + e1;
            #pragma unroll
            for (int o = 16; o > 0; o >>= 1) ssum += __shfl_xor_sync(0xffffffffu, ssum, o);
            float inv = 1.0f / ssum;
            srow[lane] = e0 * inv; srow[lane + 32] = e1 * inv;
        }
    }
    __syncthreads();

    {
        int r = tid & 15, i0 = tid >> 4;
        if (r < NREL) {
            for (int i = i0; i < 64; i += 16) {
                int rowi = i >> 3, coli = i & 7;
                int rowj = rowi - (r - 7);
                float wh = 0.f;
                if (rowj >= 0 && rowj < 8) {
                    const float* p = sc + i * 64 + rowj * 8;
                    #pragma unroll
                    for (int c = 0; c < 8; ++c) wh += p[c];
                }
                int colj = coli - (r - 7);
                float ww = 0.f;
                if (colj >= 0 && colj < 8) {
                    const float* p = sc + i * 64 + colj;
                    #pragma unroll
                    for (int rj = 0; rj < 8; ++rj) ww += p[rj * 8];
                }
                Wh[i * 16 + r] = wh; Ww[i * 16 + r] = ww;
            }
        }
    }
    __syncthreads();

    {
        int i  = tid >> 2;
        int d0 = (tid & 3) * 16;
        float c16[16];
        #pragma unroll
        for (int dd = 0; dd < 16; ++dd) c16[dd] = 0.f;
        const float* srow = sc + i * 64;
        for (int j = 0; j < 64; ++j) {
            float a = srow[j];
            const float* vr = vs + j * LDQ + d0;
            #pragma unroll
            for (int dd = 0; dd < 16; ++dd) c16[dd] = fmaf(a, vr[dd], c16[dd]);
        }
        #pragma unroll
        for (int r = 0; r < NREL; ++r) {
            float wh = Wh[i * 16 + r], ww = Ww[i * 16 + r];
            const float* eh = t_evh + r * LDE + d0;
            const float* ew = t_evw + r * LDE + d0;
            #pragma unroll
            for (int dd = 0; dd < 16; ++dd)
                c16[dd] = fmaf(wh, eh[dd], fmaf(ww, ew[dd], c16[dd]));
        }
        int b = bx >> 4, h = bx & 15;
        float* dst = g_ctx + (size_t)(b * SS + i) * DD + h * DH + d0;
        #pragma unroll
        for (int dd = 0; dd < 16; dd += 4)
            *(float4*)&dst[dd] = make_float4(c16[dd], c16[dd+1], c16[dd+2], c16[dd+3]);
    }
}

// ---------------------------------------------------------------------------
extern "C" void kernel_launch(void* const* d_in, const int* in_sizes, int n_in,
                              void* d_out, int out_size) {
    const float* x    = (const float*)d_in[0];
    const float* wq   = (const float*)d_in[1];
    const float* wk   = (const float*)d_in[2];
    const float* wv   = (const float*)d_in[3];
    const float* wo   = (const float*)d_in[4];
    const float* bo   = (const float*)d_in[5];
    const float* eq_h = (const float*)d_in[6];
    const float* eq_w = (const float*)d_in[7];
    const float* ek_h = (const float*)d_in[8];
    const float* ek_w = (const float*)d_in[9];
    const float* ev_h = (const float*)d_in[10];
    const float* ev_w = (const float*)d_in[11];
    float* out = (float*)d_out;

    cudaFuncSetAttribute(qkv_hmma, cudaFuncAttributeMaxDynamicSharedMemorySize, GEMM_SMEM);
    cudaFuncSetAttribute(out_hmma, cudaFuncAttributeMaxDynamicSharedMemorySize, GEMM_SMEM);
    cudaFuncSetAttribute(attn_kernel, cudaFuncAttributeMaxDynamicSharedMemorySize, ATT_SMEM_BYTES);

    void *p_ah = nullptr, *p_al = nullptr, *p_wh = nullptr, *p_wl = nullptr, *p_ctx = nullptr;
    cudaGetSymbolAddress(&p_ah, g_ah);
    cudaGetSymbolAddress(&p_al, g_al);
    cudaGetSymbolAddress(&p_wh, g_wh);
    cudaGetSymbolAddress(&p_wl, g_wl);
    cudaGetSymbolAddress(&p_ctx, g_ctx);
    __nv_bfloat16* wh = (__nv_bfloat16*)p_wh;
    __nv_bfloat16* wl = (__nv_bfloat16*)p_wl;

    prep_kernel<<<16, 256>>>(eq_h, eq_w, ek_h, ek_w);
    conv_split_kernel<<<8192, 256>>>(x, (__nv_bfloat16*)p_ah, (__nv_bfloat16*)p_al);
    conv_split_kernel<<<512, 256>>>(wq, wh + (size_t)0*DD*DD, wl + (size_t)0*DD*DD);
    conv_split_kernel<<<512, 256>>>(wk, wh + (size_t)1*DD*DD, wl + (size_t)1*DD*DD);
    conv_split_kernel<<<512, 256>>>(wv, wh + (size_t)2*DD*DD, wl + (size_t)2*DD*DD);
    conv_split_kernel<<<512, 256>>>(wo, wh + (size_t)3*DD*DD, wl + (size_t)3*DD*DD);

    qkv_hmma<<<dim3(24, 128), 256, GEMM_SMEM>>>(x);
    attn_kernel<<<BB * HH, 256, ATT_SMEM_BYTES>>>(eq_h, eq_w, ek_h, ek_w, ev_h, ev_w);
    conv_split_kernel<<<8192, 256>>>((const float*)p_ctx, (__nv_bfloat16*)p_ah, (__nv_bfloat16*)p_al);
    out_hmma<<<dim3(8, 128), 256, GEMM_SMEM>>>(bo, out);
}

// round 4
// speedup vs baseline: 2.0161x; 1.0506x over previous
#include <cuda_runtime.h>
#include <cuda_bf16.h>
#include <cstdint>

// Problem constants
#define BB 256
#define SS 64
#define DD 1024
#define HH 16
#define DH 64
#define NREL 15
#define MTOT (BB*SS)   // 16384

// ---------------------------------------------------------------------------
// Device scratch
// ---------------------------------------------------------------------------
__device__ __align__(1024) float g_q[(size_t)BB*HH*SS*DH];
__device__ __align__(1024) float g_k[(size_t)BB*HH*SS*DH];
__device__ __align__(1024) float g_v[(size_t)BB*HH*SS*DH];
__device__ float g_c[SS*SS];

// split-bf16 row-major buffers (activations reused: x-split, then ctx-split)
__device__ __align__(1024) __nv_bfloat16 g_ah[(size_t)MTOT*DD];
__device__ __align__(1024) __nv_bfloat16 g_al[(size_t)MTOT*DD];
__device__ __align__(1024) __nv_bfloat16 g_wh[(size_t)4*DD*DD];
__device__ __align__(1024) __nv_bfloat16 g_wl[(size_t)4*DD*DD];

// ---------------------------------------------------------------------------
// PTX helpers (arch-baseline: sm_80/75 features only — no 'a'-gated instrs)
// ---------------------------------------------------------------------------
__device__ __forceinline__ uint32_t smem_u32(const void* p) {
    uint32_t a;
    asm("{ .reg .u64 t; cvta.to.shared.u64 t, %1; cvt.u32.u64 %0, t; }" : "=r"(a) : "l"(p));
    return a;
}
__device__ __forceinline__ void cp16(uint32_t dst, const void* src) {
    asm volatile("cp.async.cg.shared.global [%0], [%1], 16;" :: "r"(dst), "l"(src));
}
__device__ __forceinline__ void cp_commit() {
    asm volatile("cp.async.commit_group;" ::: "memory");
}
template<int N> __device__ __forceinline__ void cp_wait() {
    asm volatile("cp.async.wait_group %0;" :: "n"(N) : "memory");
}
__device__ __forceinline__ void ldsm4(uint32_t (&r)[4], uint32_t a) {
    asm volatile("ldmatrix.sync.aligned.m8n8.x4.shared.b16 {%0,%1,%2,%3}, [%4];"
                 : "=r"(r[0]), "=r"(r[1]), "=r"(r[2]), "=r"(r[3]) : "r"(a));
}
__device__ __forceinline__ void mma16816(float (&c)[4], const uint32_t (&a)[4],
                                         uint32_t b0, uint32_t b1) {
    asm volatile("mma.sync.aligned.m16n8k16.row.col.f32.bf16.bf16.f32 "
                 "{%0,%1,%2,%3}, {%4,%5,%6,%7}, {%8,%9}, {%0,%1,%2,%3};"
                 : "+f"(c[0]), "+f"(c[1]), "+f"(c[2]), "+f"(c[3])
                 : "r"(a[0]), "r"(a[1]), "r"(a[2]), "r"(a[3]), "r"(b0), "r"(b1));
}

// ---------------------------------------------------------------------------
// prep: c[i][j] = (eq_h[rr]+eq_w[rc]) . (ek_h[rr]+ek_w[rc])
// ---------------------------------------------------------------------------
__global__ void prep_kernel(const float* __restrict__ eq_h, const float* __restrict__ eq_w,
                            const float* __restrict__ ek_h, const float* __restrict__ ek_w) {
    int idx = blockIdx.x * 256 + threadIdx.x;
    int i = idx >> 6, j = idx & 63;
    int rr = (i >> 3) - (j >> 3) + 7;
    int rc = (i & 7) - (j & 7) + 7;
    float acc = 0.f;
    #pragma unroll 8
    for (int d = 0; d < 64; ++d) {
        float a = eq_h[rr * 64 + d] + eq_w[rc * 64 + d];
        float b = ek_h[rr * 64 + d] + ek_w[rc * 64 + d];
        acc += a * b;
    }
    g_c[idx] = acc;
}

// ---------------------------------------------------------------------------
// fp32 -> split bf16 (hi + lo), row-major. One thread = 8 elems.
// ---------------------------------------------------------------------------
__global__ __launch_bounds__(256) void conv_split_kernel(
    const float* __restrict__ src, __nv_bfloat16* __restrict__ hi, __nv_bfloat16* __restrict__ lo) {
    size_t base = ((size_t)blockIdx.x * 256 + threadIdx.x) * 8;
    float4 a = *(const float4*)(src + base);
    float4 b = *(const float4*)(src + base + 4);
    float v[8] = {a.x, a.y, a.z, a.w, b.x, b.y, b.z, b.w};
    __nv_bfloat16 h[8], l[8];
    #pragma unroll
    for (int i = 0; i < 8; ++i) {
        h[i] = __float2bfloat16(v[i]);
        l[i] = __float2bfloat16(v[i] - __bfloat162float(h[i]));
    }
    *(uint4*)(hi + base) = *(uint4*)h;
    *(uint4*)(lo + base) = *(uint4*)l;
}

// ---------------------------------------------------------------------------
// HMMA split-bf16 GEMM core: acc(128x128) = A(128 x 1024) * B(128 x 1024)^T
// 3 terms: Ah*Bh + Ah*Bl + Al*Bh, fp32 accum. 512 threads, 16 warps (4x4),
// warp tile 32x32. 4-stage ring, 32KB/stage:
//   Ah @0, Al @8192, Bh @16384, Bl @24576; rows 64B wide,
//   16B-chunk col swizzled by ((k8 ^ (row>>1)) & 3).
// ---------------------------------------------------------------------------
#define STAGES 4
#define STAGE_BYTES 32768
#define GEMM_SMEM (STAGES * STAGE_BYTES)

__device__ __forceinline__ void gemm_acc(
    const __nv_bfloat16* __restrict__ Ahp, const __nv_bfloat16* __restrict__ Alp,
    const __nv_bfloat16* __restrict__ Bhp, const __nv_bfloat16* __restrict__ Blp,
    int mbase, int nbase, float acc[2][4][4])
{
    extern __shared__ unsigned char sm_raw[];
    uint32_t smbase = smem_u32(sm_raw);
    int tid = threadIdx.x, lane = tid & 31, wid = tid >> 5;
    int wm = (wid >> 2) * 32, wn = (wid & 3) * 32;

    #pragma unroll
    for (int i = 0; i < 2; ++i)
        #pragma unroll
        for (int j = 0; j < 4; ++j)
            #pragma unroll
            for (int e = 0; e < 4; ++e) acc[i][j][e] = 0.f;

    const __nv_bfloat16* srcA_h = Ahp + (size_t)mbase * DD;
    const __nv_bfloat16* srcA_l = Alp + (size_t)mbase * DD;
    const __nv_bfloat16* srcB_h = Bhp + (size_t)nbase * DD;
    const __nv_bfloat16* srcB_l = Blp + (size_t)nbase * DD;

    int lm  = tid >> 2;            // 0..127
    int lk8 = tid & 3;             // 16B chunk within 64B row
    uint32_t loff = (uint32_t)(lm * 64 + ((lk8 ^ (lm >> 1)) & 3) * 16);

    #define LOAD_CHUNK(kc, st) do {                                            \
        uint32_t sb_ = smbase + (st) * STAGE_BYTES;                            \
        size_t g_ = (size_t)lm * DD + (kc) * 32 + lk8 * 8;                     \
        cp16(sb_ + loff,         srcA_h + g_);                                 \
        cp16(sb_ + 8192 + loff,  srcA_l + g_);                                 \
        cp16(sb_ + 16384 + loff, srcB_h + g_);                                 \
        cp16(sb_ + 24576 + loff, srcB_l + g_);                                 \
        cp_commit();                                                           \
    } while (0)

    LOAD_CHUNK(0, 0);
    LOAD_CHUNK(1, 1);
    LOAD_CHUNK(2, 2);

    int arow = wm + (lane & 7) + ((lane >> 3) & 1) * 8;
    int brow = wn + (lane & 7) + ((lane >> 3) & 1) * 8;
    int k8l  = (lane >> 4);   // 0 or 1; actual k8 = 2*s16 + k8l

    for (int kc = 0; kc < 32; ++kc) {
        cp_wait<2>();
        __syncthreads();
        if (kc + 3 < 32) LOAD_CHUNK(kc + 3, (kc + 3) & 3);
        else             cp_commit();
        uint32_t sb = smbase + (kc & 3) * STAGE_BYTES;

        #pragma unroll
        for (int s16 = 0; s16 < 2; ++s16) {
            int k8 = 2 * s16 + k8l;
            uint32_t ah[2][4], al[2][4];
            #pragma unroll
            for (int i = 0; i < 2; ++i) {
                int r = arow + i * 16;
                uint32_t ad = sb + (uint32_t)(r * 64 + ((k8 ^ (r >> 1)) & 3) * 16);
                ldsm4(ah[i], ad);
                ldsm4(al[i], ad + 8192);
            }
            uint32_t bh[2][4], bl[2][4];
            #pragma unroll
            for (int jp = 0; jp < 2; ++jp) {
                int r = brow + jp * 16;
                uint32_t ad = sb + 16384 + (uint32_t)(r * 64 + ((k8 ^ (r >> 1)) & 3) * 16);
                ldsm4(bh[jp], ad);
                ldsm4(bl[jp], ad + 8192);
            }
            #pragma unroll
            for (int i = 0; i < 2; ++i)
                #pragma unroll
                for (int j = 0; j < 4; ++j) {
                    uint32_t bh0 = bh[j >> 1][j & 1], bh1 = bh[j >> 1][(j & 1) + 2];
                    uint32_t bl0 = bl[j >> 1][j & 1], bl1 = bl[j >> 1][(j & 1) + 2];
                    mma16816(acc[i][j], ah[i], bh0, bh1);
                    mma16816(acc[i][j], ah[i], bl0, bl1);
                    mma16816(acc[i][j], al[i], bh0, bh1);
                }
        }
    }
    #undef LOAD_CHUNK
}

// ---------------------------------------------------------------------------
// QKV GEMM: grid (24, 128). nt>>3 selects q/k/v, (nt&7)*128 = n0.
// ---------------------------------------------------------------------------
__global__ __launch_bounds__(512, 1) void qkv_hmma() {
    int nt = blockIdx.x, mt = blockIdx.y;
    int which = nt >> 3, nq = nt & 7;
    float acc[2][4][4];
    gemm_acc(g_ah, g_al, g_wh + (size_t)which * DD * DD, g_wl + (size_t)which * DD * DD,
             mt * 128, nq * 128, acc);

    float* dst = (which == 0) ? g_q : (which == 1) ? g_k : g_v;
    int lane = threadIdx.x & 31, wid = threadIdx.x >> 5;
    int wm = (wid >> 2) * 32, wn = (wid & 3) * 32;
    int l4 = lane >> 2, l2 = (lane & 3) * 2;

    #pragma unroll
    for (int i = 0; i < 2; ++i)
        #pragma unroll
        for (int j = 0; j < 4; ++j) {
            int m = mt * 128 + wm + i * 16 + l4;
            int n = nq * 128 + wn + j * 8 + l2;
            int h = n >> 6, d = n & 63;
            int b = m >> 6, s = m & 63;
            *(float2*)&dst[(((size_t)(b * HH + h) * SS + s) << 6) + d] =
                make_float2(acc[i][j][0], acc[i][j][1]);
            *(float2*)&dst[(((size_t)(b * HH + h) * SS + (s + 8)) << 6) + d] =
                make_float2(acc[i][j][2], acc[i][j][3]);
        }
}

// ---------------------------------------------------------------------------
// Output GEMM: grid (8, 128). out = ctx @ wo^T + bo
// ---------------------------------------------------------------------------
__global__ __launch_bounds__(512, 1) void out_hmma(const float* __restrict__ bo,
                                                   float* __restrict__ out) {
    int nt = blockIdx.x, mt = blockIdx.y;
    float acc[2][4][4];
    gemm_acc(g_ah, g_al, g_wh + (size_t)3 * DD * DD, g_wl + (size_t)3 * DD * DD,
             mt * 128, nt * 128, acc);

    int lane = threadIdx.x & 31, wid = threadIdx.x >> 5;
    int wm = (wid >> 2) * 32, wn = (wid & 3) * 32;
    int l4 = lane >> 2, l2 = (lane & 3) * 2;

    #pragma unroll
    for (int i = 0; i < 2; ++i)
        #pragma unroll
        for (int j = 0; j < 4; ++j) {
            int m = mt * 128 + wm + i * 16 + l4;
            int n = nt * 128 + wn + j * 8 + l2;
            float b0 = __ldg(bo + n), b1 = __ldg(bo + n + 1);
            *(float2*)&out[(size_t)m * DD + n] =
                make_float2(acc[i][j][0] + b0, acc[i][j][1] + b1);
            *(float2*)&out[(size_t)(m + 8) * DD + n] =
                make_float2(acc[i][j][2] + b0, acc[i][j][3] + b1);
        }
}

// ---------------------------------------------------------------------------
// Attention: one block per (b,h). Epilogue writes split-bf16 ctx directly.
// ---------------------------------------------------------------------------
#define LDQ 68
#define LDE 65
#define ATT_SMEM_FLOATS (3*64*LDQ + 4096 + 6*NREL*LDE + 6*1024)
#define ATT_SMEM_BYTES  (ATT_SMEM_FLOATS * 4)

__global__ __launch_bounds__(256) void attn_kernel(
    const float* __restrict__ eq_h, const float* __restrict__ eq_w,
    const float* __restrict__ ek_h, const float* __restrict__ ek_w,
    const float* __restrict__ ev_h, const float* __restrict__ ev_w)
{
    extern __shared__ float sm[];
    float* qs    = sm;
    float* ks    = qs + 64 * LDQ;
    float* vs    = ks + 64 * LDQ;
    float* sc    = vs + 64 * LDQ;
    float* t_ekh = sc + 4096;
    float* t_ekw = t_ekh + NREL * LDE;
    float* t_eqh = t_ekw + NREL * LDE;
    float* t_eqw = t_eqh + NREL * LDE;
    float* t_evh = t_eqw + NREL * LDE;
    float* t_evw = t_evh + NREL * LDE;
    float* Ah    = t_evw + NREL * LDE;
    float* Aw    = Ah + 1024;
    float* Ch    = Aw + 1024;
    float* Cw    = Ch + 1024;
    float* Wh    = Cw + 1024;
    float* Ww    = Wh + 1024;

    int tid = threadIdx.x;
    int bx  = blockIdx.x;
    size_t base = (size_t)bx * (SS * DH);

    #pragma unroll
    for (int it = 0; it < 4; ++it) {
        int e = tid * 4 + it * 1024;
        int s = e >> 6, d = e & 63;
        *(float4*)&qs[s * LDQ + d] = *(const float4*)&g_q[base + e];
        *(float4*)&ks[s * LDQ + d] = *(const float4*)&g_k[base + e];
        *(float4*)&vs[s * LDQ + d] = *(const float4*)&g_v[base + e];
    }
    for (int idx = tid; idx < NREL * 64; idx += 256) {
        int r = idx >> 6, d = idx & 63;
        int o = r * LDE + d;
        t_ekh[o] = ek_h[idx]; t_ekw[o] = ek_w[idx];
        t_eqh[o] = eq_h[idx]; t_eqw[o] = eq_w[idx];
        t_evh[o] = ev_h[idx]; t_evw[o] = ev_w[idx];
    }
    __syncthreads();

    {
        int r = tid & 15, i0 = tid >> 4;
        if (r < NREL) {
            for (int i = i0; i < 64; i += 16) {
                const float* qrow = qs + i * LDQ;
                const float* krow = ks + i * LDQ;
                const float* ekh = t_ekh + r * LDE; const float* ekw = t_ekw + r * LDE;
                const float* eqh = t_eqh + r * LDE; const float* eqw = t_eqw + r * LDE;
                float ah = 0.f, aw = 0.f, ch = 0.f, cw = 0.f;
                #pragma unroll 8
                for (int d = 0; d < 64; ++d) {
                    float qv = qrow[d], kv = krow[d];
                    ah = fmaf(qv, ekh[d], ah);
                    aw = fmaf(qv, ekw[d], aw);
                    ch = fmaf(kv, eqh[d], ch);
                    cw = fmaf(kv, eqw[d], cw);
                }
                Ah[i * 16 + r] = ah; Aw[i * 16 + r] = aw;
                Ch[i * 16 + r] = ch; Cw[i * 16 + r] = cw;
            }
        }
    }
    __syncthreads();

    {
        int ti = tid >> 4, tj = tid & 15;
        float accv[4][4];
        #pragma unroll
        for (int a = 0; a < 4; ++a)
            #pragma unroll
            for (int b = 0; b < 4; ++b) accv[a][b] = 0.f;
        const float* qa = qs + (ti * 4) * LDQ;
        const float* kb = ks + (tj * 4) * LDQ;
        #pragma unroll 4
        for (int d = 0; d < 64; ++d) {
            float a0 = qa[d], a1 = qa[LDQ + d], a2 = qa[2 * LDQ + d], a3 = qa[3 * LDQ + d];
            float b0 = kb[d], b1 = kb[LDQ + d], b2 = kb[2 * LDQ + d], b3 = kb[3 * LDQ + d];
            accv[0][0] = fmaf(a0, b0, accv[0][0]); accv[0][1] = fmaf(a0, b1, accv[0][1]);
            accv[0][2] = fmaf(a0, b2, accv[0][2]); accv[0][3] = fmaf(a0, b3, accv[0][3]);
            accv[1][0] = fmaf(a1, b0, accv[1][0]); accv[1][1] = fmaf(a1, b1, accv[1][1]);
            accv[1][2] = fmaf(a1, b2, accv[1][2]); accv[1][3] = fmaf(a1, b3, accv[1][3]);
            accv[2][0] = fmaf(a2, b0, accv[2][0]); accv[2][1] = fmaf(a2, b1, accv[2][1]);
            accv[2][2] = fmaf(a2, b2, accv[2][2]); accv[2][3] = fmaf(a2, b3, accv[2][3]);
            accv[3][0] = fmaf(a3, b0, accv[3][0]); accv[3][1] = fmaf(a3, b1, accv[3][1]);
            accv[3][2] = fmaf(a3, b2, accv[3][2]); accv[3][3] = fmaf(a3, b3, accv[3][3]);
        }
        #pragma unroll
        for (int ii = 0; ii < 4; ++ii)
            #pragma unroll
            for (int jj = 0; jj < 4; ++jj) {
                int i = ti * 4 + ii, j = tj * 4 + jj;
                int rr = (i >> 3) - (j >> 3) + 7;
                int rc = (i & 7) - (j & 7) + 7;
                float sv = accv[ii][jj] + Ah[i * 16 + rr] + Aw[i * 16 + rc]
                         + Ch[j * 16 + rr] + Cw[j * 16 + rc] + __ldg(&g_c[i * 64 + j]);
                sc[i * 64 + j] = sv * 0.125f;
            }
    }
    __syncthreads();

    {
        int wid = tid >> 5, lane = tid & 31;
        for (int row = wid; row < 64; row += 8) {
            float* srow = sc + row * 64;
            float x0 = srow[lane], x1 = srow[lane + 32];
            float m = fmaxf(x0, x1);
            #pragma unroll
            for (int o = 16; o > 0; o >>= 1) m = fmaxf(m, __shfl_xor_sync(0xffffffffu, m, o));
            float e0 = __expf(x0 - m), e1 = __expf(x1 - m);
            float ssum = e0 + e1;
            #pragma unroll
            for (int o = 16; o > 0; o >>= 1) ssum += __shfl_xor_sync(0xffffffffu, ssum, o);
            float inv = 1.0f / ssum;
            srow[lane] = e0 * inv; srow[lane + 32] = e1 * inv;
        }
    }
    __syncthreads();

    {
        int r = tid & 15, i0 = tid >> 4;
        if (r < NREL) {
            for (int i = i0; i < 64; i += 16) {
                int rowi = i >> 3, coli = i & 7;
                int rowj = rowi - (r - 7);
                float wh = 0.f;
                if (rowj >= 0 && rowj < 8) {
                    const float* p = sc + i * 64 + rowj * 8;
                    #pragma unroll
                    for (int c = 0; c < 8; ++c) wh += p[c];
                }
                int colj = coli - (r - 7);
                float ww = 0.f;
                if (colj >= 0 && colj < 8) {
                    const float* p = sc + i * 64 + colj;
                    #pragma unroll
                    for (int rj = 0; rj < 8; ++rj) ww += p[rj * 8];
                }
                Wh[i * 16 + r] = wh; Ww[i * 16 + r] = ww;
            }
        }
    }
    __syncthreads();

    {
        int i  = tid >> 2;
        int d0 = (tid & 3) * 16;
        float c16[16];
        #pragma unroll
        for (int dd = 0; dd < 16; ++dd) c16[dd] = 0.f;
        const float* srow = sc + i * 64;
        for (int j = 0; j < 64; ++j) {
            float a = srow[j];
            const float* vr = vs + j * LDQ + d0;
            #pragma unroll
            for (int dd = 0; dd < 16; ++dd) c16[dd] = fmaf(a, vr[dd], c16[dd]);
        }
        #pragma unroll
        for (int r = 0; r < NREL; ++r) {
            float wh = Wh[i * 16 + r], ww = Ww[i * 16 + r];
            const float* eh = t_evh + r * LDE + d0;
            const float* ew = t_evw + r * LDE + d0;
            #pragma unroll
            for (int dd = 0; dd < 16; ++dd)
                c16[dd] = fmaf(wh, eh[dd], fmaf(ww, ew[dd], c16[dd]));
        }
        // split-bf16 write (fused conversion)
        __nv_bfloat16 hv[16], lv[16];
        #pragma unroll
        for (int dd = 0; dd < 16; ++dd) {
            hv[dd] = __float2bfloat16(c16[dd]);
            lv[dd] = __float2bfloat16(c16[dd] - __bfloat162float(hv[dd]));
        }
        int b = bx >> 4, h = bx & 15;
        size_t off = (size_t)(b * SS + i) * DD + h * DH + d0;
        *(uint4*)&g_ah[off]     = *(uint4*)&hv[0];
        *(uint4*)&g_ah[off + 8] = *(uint4*)&hv[8];
        *(uint4*)&g_al[off]     = *(uint4*)&lv[0];
        *(uint4*)&g_al[off + 8] = *(uint4*)&lv[8];
    }
}

// ---------------------------------------------------------------------------
extern "C" void kernel_launch(void* const* d_in, const int* in_sizes, int n_in,
                              void* d_out, int out_size) {
    const float* x    = (const float*)d_in[0];
    const float* wq   = (const float*)d_in[1];
    const float* wk   = (const float*)d_in[2];
    const float* wv   = (const float*)d_in[3];
    const float* wo   = (const float*)d_in[4];
    const float* bo   = (const float*)d_in[5];
    const float* eq_h = (const float*)d_in[6];
    const float* eq_w = (const float*)d_in[7];
    const float* ek_h = (const float*)d_in[8];
    const float* ek_w = (const float*)d_in[9];
    const float* ev_h = (const float*)d_in[10];
    const float* ev_w = (const float*)d_in[11];
    float* out = (float*)d_out;

    cudaFuncSetAttribute(qkv_hmma, cudaFuncAttributeMaxDynamicSharedMemorySize, GEMM_SMEM);
    cudaFuncSetAttribute(out_hmma, cudaFuncAttributeMaxDynamicSharedMemorySize, GEMM_SMEM);
    cudaFuncSetAttribute(attn_kernel, cudaFuncAttributeMaxDynamicSharedMemorySize, ATT_SMEM_BYTES);

    void *p_ah = nullptr, *p_al = nullptr, *p_wh = nullptr, *p_wl = nullptr;
    cudaGetSymbolAddress(&p_ah, g_ah);
    cudaGetSymbolAddress(&p_al, g_al);
    cudaGetSymbolAddress(&p_wh, g_wh);
    cudaGetSymbolAddress(&p_wl, g_wl);
    __nv_bfloat16* wh = (__nv_bfloat16*)p_wh;
    __nv_bfloat16* wl = (__nv_bfloat16*)p_wl;

    prep_kernel<<<16, 256>>>(eq_h, eq_w, ek_h, ek_w);
    conv_split_kernel<<<8192, 256>>>(x, (__nv_bfloat16*)p_ah, (__nv_bfloat16*)p_al);
    conv_split_kernel<<<512, 256>>>(wq, wh + (size_t)0*DD*DD, wl + (size_t)0*DD*DD);
    conv_split_kernel<<<512, 256>>>(wk, wh + (size_t)1*DD*DD, wl + (size_t)1*DD*DD);
    conv_split_kernel<<<512, 256>>>(wv, wh + (size_t)2*DD*DD, wl + (size_t)2*DD*DD);
    conv_split_kernel<<<512, 256>>>(wo, wh + (size_t)3*DD*DD, wl + (size_t)3*DD*DD);

    qkv_hmma<<<dim3(24, 128), 512, GEMM_SMEM>>>();
    attn_kernel<<<BB * HH, 256, ATT_SMEM_BYTES>>>(eq_h, eq_w, ek_h, ek_w, ev_h, ev_w);
    out_hmma<<<dim3(8, 128), 512, GEMM_SMEM>>>(bo, out);
}

// round 5
// speedup vs baseline: 2.4455x; 1.2130x over previous
#include <cuda_runtime.h>
#include <cuda_fp16.h>
#include <cstdint>

// Problem constants
#define BB 256
#define SS 64
#define DD 1024
#define HH 16
#define DH 64
#define NREL 15
#define MTOT (BB*SS)   // 16384

// ---------------------------------------------------------------------------
// Device scratch
// ---------------------------------------------------------------------------
__device__ __align__(1024) float g_q[(size_t)BB*HH*SS*DH];
__device__ __align__(1024) float g_k[(size_t)BB*HH*SS*DH];
__device__ __align__(1024) float g_v[(size_t)BB*HH*SS*DH];
__device__ float g_c[SS*SS];

// fp16 buffers: activations single, weights split hi+lo
__device__ __align__(1024) __half g_a [(size_t)MTOT*DD];      // x, then ctx (fp16)
__device__ __align__(1024) __half g_wh[(size_t)4*DD*DD];      // weights hi
__device__ __align__(1024) __half g_wl[(size_t)4*DD*DD];      // weights lo

// ---------------------------------------------------------------------------
// PTX helpers (arch-baseline: sm_80/75 features only)
// ---------------------------------------------------------------------------
__device__ __forceinline__ uint32_t smem_u32(const void* p) {
    uint32_t a;
    asm("{ .reg .u64 t; cvta.to.shared.u64 t, %1; cvt.u32.u64 %0, t; }" : "=r"(a) : "l"(p));
    return a;
}
__device__ __forceinline__ void cp16(uint32_t dst, const void* src) {
    asm volatile("cp.async.cg.shared.global [%0], [%1], 16;" :: "r"(dst), "l"(src));
}
__device__ __forceinline__ void cp_commit() {
    asm volatile("cp.async.commit_group;" ::: "memory");
}
template<int N> __device__ __forceinline__ void cp_wait() {
    asm volatile("cp.async.wait_group %0;" :: "n"(N) : "memory");
}
__device__ __forceinline__ void ldsm4(uint32_t (&r)[4], uint32_t a) {
    asm volatile("ldmatrix.sync.aligned.m8n8.x4.shared.b16 {%0,%1,%2,%3}, [%4];"
                 : "=r"(r[0]), "=r"(r[1]), "=r"(r[2]), "=r"(r[3]) : "r"(a));
}
__device__ __forceinline__ void mma16816(float (&c)[4], const uint32_t (&a)[4],
                                         uint32_t b0, uint32_t b1) {
    asm volatile("mma.sync.aligned.m16n8k16.row.col.f32.f16.f16.f32 "
                 "{%0,%1,%2,%3}, {%4,%5,%6,%7}, {%8,%9}, {%0,%1,%2,%3};"
                 : "+f"(c[0]), "+f"(c[1]), "+f"(c[2]), "+f"(c[3])
                 : "r"(a[0]), "r"(a[1]), "r"(a[2]), "r"(a[3]), "r"(b0), "r"(b1));
}

// ---------------------------------------------------------------------------
// prep: c[i][j] = (eq_h[rr]+eq_w[rc]) . (ek_h[rr]+ek_w[rc])
// ---------------------------------------------------------------------------
__global__ void prep_kernel(const float* __restrict__ eq_h, const float* __restrict__ eq_w,
                            const float* __restrict__ ek_h, const float* __restrict__ ek_w) {
    int idx = blockIdx.x * 256 + threadIdx.x;
    int i = idx >> 6, j = idx & 63;
    int rr = (i >> 3) - (j >> 3) + 7;
    int rc = (i & 7) - (j & 7) + 7;
    float acc = 0.f;
    #pragma unroll 8
    for (int d = 0; d < 64; ++d) {
        float a = eq_h[rr * 64 + d] + eq_w[rc * 64 + d];
        float b = ek_h[rr * 64 + d] + ek_w[rc * 64 + d];
        acc += a * b;
    }
    g_c[idx] = acc;
}

// ---------------------------------------------------------------------------
// fp32 -> fp16 (single). One thread = 8 elems.
// ---------------------------------------------------------------------------
__global__ __launch_bounds__(256) void conv_act_kernel(
    const float* __restrict__ src, __half* __restrict__ dst) {
    size_t base = ((size_t)blockIdx.x * 256 + threadIdx.x) * 8;
    float4 a = *(const float4*)(src + base);
    float4 b = *(const float4*)(src + base + 4);
    float v[8] = {a.x, a.y, a.z, a.w, b.x, b.y, b.z, b.w};
    __half h[8];
    #pragma unroll
    for (int i = 0; i < 8; ++i) h[i] = __float2half(v[i]);
    *(uint4*)(dst + base) = *(uint4*)h;
}

// fp32 -> split fp16 (hi + lo). One thread = 8 elems.
__global__ __launch_bounds__(256) void conv_wsplit_kernel(
    const float* __restrict__ src, __half* __restrict__ hi, __half* __restrict__ lo) {
    size_t base = ((size_t)blockIdx.x * 256 + threadIdx.x) * 8;
    float4 a = *(const float4*)(src + base);
    float4 b = *(const float4*)(src + base + 4);
    float v[8] = {a.x, a.y, a.z, a.w, b.x, b.y, b.z, b.w};
    __half h[8], l[8];
    #pragma unroll
    for (int i = 0; i < 8; ++i) {
        h[i] = __float2half(v[i]);
        l[i] = __float2half(v[i] - __half2float(h[i]));
    }
    *(uint4*)(hi + base) = *(uint4*)h;
    *(uint4*)(lo + base) = *(uint4*)l;
}

// ---------------------------------------------------------------------------
// HMMA fp16 2-term GEMM core: acc(128x128) = A(128x1024) * (Wh+Wl)(128x1024)^T
// 512 threads, 16 warps (4x4), warp tile 32x32. 4-stage ring, 24KB/stage:
//   A @0, Bh @8192, Bl @16384; rows 64B wide,
//   16B-chunk col swizzled by ((k8 ^ (row>>1)) & 3).
// ---------------------------------------------------------------------------
#define STAGES 4
#define STAGE_BYTES 24576
#define GEMM_SMEM (STAGES * STAGE_BYTES)

__device__ __forceinline__ void gemm_acc(
    const __half* __restrict__ Ap,
    const __half* __restrict__ Bhp, const __half* __restrict__ Blp,
    int mbase, int nbase, float acc[2][4][4])
{
    extern __shared__ unsigned char sm_raw[];
    uint32_t smbase = smem_u32(sm_raw);
    int tid = threadIdx.x, lane = tid & 31, wid = tid >> 5;
    int wm = (wid >> 2) * 32, wn = (wid & 3) * 32;

    #pragma unroll
    for (int i = 0; i < 2; ++i)
        #pragma unroll
        for (int j = 0; j < 4; ++j)
            #pragma unroll
            for (int e = 0; e < 4; ++e) acc[i][j][e] = 0.f;

    const __half* srcA  = Ap  + (size_t)mbase * DD;
    const __half* srcBh = Bhp + (size_t)nbase * DD;
    const __half* srcBl = Blp + (size_t)nbase * DD;

    int lm  = tid >> 2;            // 0..127
    int lk8 = tid & 3;             // 16B chunk within 64B row
    uint32_t loff = (uint32_t)(lm * 64 + ((lk8 ^ (lm >> 1)) & 3) * 16);

    #define LOAD_CHUNK(kc, st) do {                                            \
        uint32_t sb_ = smbase + (st) * STAGE_BYTES;                            \
        size_t g_ = (size_t)lm * DD + (kc) * 32 + lk8 * 8;                     \
        cp16(sb_ + loff,         srcA  + g_);                                  \
        cp16(sb_ + 8192 + loff,  srcBh + g_);                                  \
        cp16(sb_ + 16384 + loff, srcBl + g_);                                  \
        cp_commit();                                                           \
    } while (0)

    LOAD_CHUNK(0, 0);
    LOAD_CHUNK(1, 1);
    LOAD_CHUNK(2, 2);

    int arow = wm + (lane & 7) + ((lane >> 3) & 1) * 8;
    int brow = wn + (lane & 7) + ((lane >> 3) & 1) * 8;
    int k8l  = (lane >> 4);   // 0 or 1; actual k8 = 2*s16 + k8l

    for (int kc = 0; kc < 32; ++kc) {
        cp_wait<2>();
        __syncthreads();
        if (kc + 3 < 32) LOAD_CHUNK(kc + 3, (kc + 3) & 3);
        else             cp_commit();
        uint32_t sb = smbase + (kc & 3) * STAGE_BYTES;

        #pragma unroll
        for (int s16 = 0; s16 < 2; ++s16) {
            int k8 = 2 * s16 + k8l;
            uint32_t av[2][4];
            #pragma unroll
            for (int i = 0; i < 2; ++i) {
                int r = arow + i * 16;
                uint32_t ad = sb + (uint32_t)(r * 64 + ((k8 ^ (r >> 1)) & 3) * 16);
                ldsm4(av[i], ad);
            }
            uint32_t bh[2][4], bl[2][4];
            #pragma unroll
            for (int jp = 0; jp < 2; ++jp) {
                int r = brow + jp * 16;
                uint32_t ad = sb + 8192 + (uint32_t)(r * 64 + ((k8 ^ (r >> 1)) & 3) * 16);
                ldsm4(bh[jp], ad);
                ldsm4(bl[jp], ad + 8192);
            }
            #pragma unroll
            for (int i = 0; i < 2; ++i)
                #pragma unroll
                for (int j = 0; j < 4; ++j) {
                    uint32_t bh0 = bh[j >> 1][j & 1], bh1 = bh[j >> 1][(j & 1) + 2];
                    uint32_t bl0 = bl[j >> 1][j & 1], bl1 = bl[j >> 1][(j & 1) + 2];
                    mma16816(acc[i][j], av[i], bh0, bh1);
                    mma16816(acc[i][j], av[i], bl0, bl1);
                }
        }
    }
    #undef LOAD_CHUNK
}

// ---------------------------------------------------------------------------
// QKV GEMM: grid (24, 128). nt>>3 selects q/k/v, (nt&7)*128 = n0.
// ---------------------------------------------------------------------------
__global__ __launch_bounds__(512, 1) void qkv_hmma() {
    int nt = blockIdx.x, mt = blockIdx.y;
    int which = nt >> 3, nq = nt & 7;
    float acc[2][4][4];
    gemm_acc(g_a, g_wh + (size_t)which * DD * DD, g_wl + (size_t)which * DD * DD,
             mt * 128, nq * 128, acc);

    float* dst = (which == 0) ? g_q : (which == 1) ? g_k : g_v;
    int lane = threadIdx.x & 31, wid = threadIdx.x >> 5;
    int wm = (wid >> 2) * 32, wn = (wid & 3) * 32;
    int l4 = lane >> 2, l2 = (lane & 3) * 2;

    #pragma unroll
    for (int i = 0; i < 2; ++i)
        #pragma unroll
        for (int j = 0; j < 4; ++j) {
            int m = mt * 128 + wm + i * 16 + l4;
            int n = nq * 128 + wn + j * 8 + l2;
            int h = n >> 6, d = n & 63;
            int b = m >> 6, s = m & 63;
            *(float2*)&dst[(((size_t)(b * HH + h) * SS + s) << 6) + d] =
                make_float2(acc[i][j][0], acc[i][j][1]);
            *(float2*)&dst[(((size_t)(b * HH + h) * SS + (s + 8)) << 6) + d] =
                make_float2(acc[i][j][2], acc[i][j][3]);
        }
}

// ---------------------------------------------------------------------------
// Output GEMM: grid (8, 128). out = ctx @ wo^T + bo
// ---------------------------------------------------------------------------
__global__ __launch_bounds__(512, 1) void out_hmma(const float* __restrict__ bo,
                                                   float* __restrict__ out) {
    int nt = blockIdx.x, mt = blockIdx.y;
    float acc[2][4][4];
    gemm_acc(g_a, g_wh + (size_t)3 * DD * DD, g_wl + (size_t)3 * DD * DD,
             mt * 128, nt * 128, acc);

    int lane = threadIdx.x & 31, wid = threadIdx.x >> 5;
    int wm = (wid >> 2) * 32, wn = (wid & 3) * 32;
    int l4 = lane >> 2, l2 = (lane & 3) * 2;

    #pragma unroll
    for (int i = 0; i < 2; ++i)
        #pragma unroll
        for (int j = 0; j < 4; ++j) {
            int m = mt * 128 + wm + i * 16 + l4;
            int n = nt * 128 + wn + j * 8 + l2;
            float b0 = __ldg(bo + n), b1 = __ldg(bo + n + 1);
            *(float2*)&out[(size_t)m * DD + n] =
                make_float2(acc[i][j][0] + b0, acc[i][j][1] + b1);
            *(float2*)&out[(size_t)(m + 8) * DD + n] =
                make_float2(acc[i][j][2] + b0, acc[i][j][3] + b1);
        }
}

// ---------------------------------------------------------------------------
// Attention: one block per (b,h). Epilogue writes fp16 ctx directly.
// ---------------------------------------------------------------------------
#define LDQ 68
#define LDE 65
#define ATT_SMEM_FLOATS (3*64*LDQ + 4096 + 6*NREL*LDE + 6*1024)
#define ATT_SMEM_BYTES  (ATT_SMEM_FLOATS * 4)

__global__ __launch_bounds__(256) void attn_kernel(
    const float* __restrict__ eq_h, const float* __restrict__ eq_w,
    const float* __restrict__ ek_h, const float* __restrict__ ek_w,
    const float* __restrict__ ev_h, const float* __restrict__ ev_w)
{
    extern __shared__ float sm[];
    float* qs    = sm;
    float* ks    = qs + 64 * LDQ;
    float* vs    = ks + 64 * LDQ;
    float* sc    = vs + 64 * LDQ;
    float* t_ekh = sc + 4096;
    float* t_ekw = t_ekh + NREL * LDE;
    float* t_eqh = t_ekw + NREL * LDE;
    float* t_eqw = t_eqh + NREL * LDE;
    float* t_evh = t_eqw + NREL * LDE;
    float* t_evw = t_evh + NREL * LDE;
    float* Ah    = t_evw + NREL * LDE;
    float* Aw    = Ah + 1024;
    float* Ch    = Aw + 1024;
    float* Cw    = Ch + 1024;
    float* Wh    = Cw + 1024;
    float* Ww    = Wh + 1024;

    int tid = threadIdx.x;
    int bx  = blockIdx.x;
    size_t base = (size_t)bx * (SS * DH);

    #pragma unroll
    for (int it = 0; it < 4; ++it) {
        int e = tid * 4 + it * 1024;
        int s = e >> 6, d = e & 63;
        *(float4*)&qs[s * LDQ + d] = *(const float4*)&g_q[base + e];
        *(float4*)&ks[s * LDQ + d] = *(const float4*)&g_k[base + e];
        *(float4*)&vs[s * LDQ + d] = *(const float4*)&g_v[base + e];
    }
    for (int idx = tid; idx < NREL * 64; idx += 256) {
        int r = idx >> 6, d = idx & 63;
        int o = r * LDE + d;
        t_ekh[o] = ek_h[idx]; t_ekw[o] = ek_w[idx];
        t_eqh[o] = eq_h[idx]; t_eqw[o] = eq_w[idx];
        t_evh[o] = ev_h[idx]; t_evw[o] = ev_w[idx];
    }
    __syncthreads();

    {
        int r = tid & 15, i0 = tid >> 4;
        if (r < NREL) {
            for (int i = i0; i < 64; i += 16) {
                const float* qrow = qs + i * LDQ;
                const float* krow = ks + i * LDQ;
                const float* ekh = t_ekh + r * LDE; const float* ekw = t_ekw + r * LDE;
                const float* eqh = t_eqh + r * LDE; const float* eqw = t_eqw + r * LDE;
                float ah = 0.f, aw = 0.f, ch = 0.f, cw = 0.f;
                #pragma unroll 8
                for (int d = 0; d < 64; ++d) {
                    float qv = qrow[d], kv = krow[d];
                    ah = fmaf(qv, ekh[d], ah);
                    aw = fmaf(qv, ekw[d], aw);
                    ch = fmaf(kv, eqh[d], ch);
                    cw = fmaf(kv, eqw[d], cw);
                }
                Ah[i * 16 + r] = ah; Aw[i * 16 + r] = aw;
                Ch[i * 16 + r] = ch; Cw[i * 16 + r] = cw;
            }
        }
    }
    __syncthreads();

    {
        int ti = tid >> 4, tj = tid & 15;
        float accv[4][4];
        #pragma unroll
        for (int a = 0; a < 4; ++a)
            #pragma unroll
            for (int b = 0; b < 4; ++b) accv[a][b] = 0.f;
        const float* qa = qs + (ti * 4) * LDQ;
        const float* kb = ks + (tj * 4) * LDQ;
        #pragma unroll 4
        for (int d = 0; d < 64; ++d) {
            float a0 = qa[d], a1 = qa[LDQ + d], a2 = qa[2 * LDQ + d], a3 = qa[3 * LDQ + d];
            float b0 = kb[d], b1 = kb[LDQ + d], b2 = kb[2 * LDQ + d], b3 = kb[3 * LDQ + d];
            accv[0][0] = fmaf(a0, b0, accv[0][0]); accv[0][1] = fmaf(a0, b1, accv[0][1]);
            accv[0][2] = fmaf(a0, b2, accv[0][2]); accv[0][3] = fmaf(a0, b3, accv[0][3]);
            accv[1][0] = fmaf(a1, b0, accv[1][0]); accv[1][1] = fmaf(a1, b1, accv[1][1]);
            accv[1][2] = fmaf(a1, b2, accv[1][2]); accv[1][3] = fmaf(a1, b3, accv[1][3]);
            accv[2][0] = fmaf(a2, b0, accv[2][0]); accv[2][1] = fmaf(a2, b1, accv[2][1]);
            accv[2][2] = fmaf(a2, b2, accv[2][2]); accv[2][3] = fmaf(a2, b3, accv[2][3]);
            accv[3][0] = fmaf(a3, b0, accv[3][0]); accv[3][1] = fmaf(a3, b1, accv[3][1]);
            accv[3][2] = fmaf(a3, b2, accv[3][2]); accv[3][3] = fmaf(a3, b3, accv[3][3]);
        }
        #pragma unroll
        for (int ii = 0; ii < 4; ++ii)
            #pragma unroll
            for (int jj = 0; jj < 4; ++jj) {
                int i = ti * 4 + ii, j = tj * 4 + jj;
                int rr = (i >> 3) - (j >> 3) + 7;
                int rc = (i & 7) - (j & 7) + 7;
                float sv = accv[ii][jj] + Ah[i * 16 + rr] + Aw[i * 16 + rc]
                         + Ch[j * 16 + rr] + Cw[j * 16 + rc] + __ldg(&g_c[i * 64 + j]);
                sc[i * 64 + j] = sv * 0.125f;
            }
    }
    __syncthreads();

    {
        int wid = tid >> 5, lane = tid & 31;
        for (int row = wid; row < 64; row += 8) {
            float* srow = sc + row * 64;
            float x0 = srow[lane], x1 = srow[lane + 32];
            float m = fmaxf(x0, x1);
            #pragma unroll
            for (int o = 16; o > 0; o >>= 1) m = fmaxf(m, __shfl_xor_sync(0xffffffffu, m, o));
            float e0 = __expf(x0 - m), e1 = __expf(x1 - m);
            float ssum = e0 + e1;
            #pragma unroll
            for (int o = 16; o > 0; o >>= 1) ssum += __shfl_xor_sync(0xffffffffu, ssum, o);
            float inv = 1.0f / ssum;
            srow[lane] = e0 * inv; srow[lane + 32] = e1 * inv;
        }
    }
    __syncthreads();

    {
        int r = tid & 15, i0 = tid >> 4;
        if (r < NREL) {
            for (int i = i0; i < 64; i += 16) {
                int rowi = i >> 3, coli = i & 7;
                int rowj = rowi - (r - 7);
                float wh = 0.f;
                if (rowj >= 0 && rowj < 8) {
                    const float* p = sc + i * 64 + rowj * 8;
                    #pragma unroll
                    for (int c = 0; c < 8; ++c) wh += p[c];
                }
                int colj = coli - (r - 7);
                float ww = 0.f;
                if (colj >= 0 && colj < 8) {
                    const float* p = sc + i * 64 + colj;
                    #pragma unroll
                    for (int rj = 0; rj < 8; ++rj) ww += p[rj * 8];
                }
                Wh[i * 16 + r] = wh; Ww[i * 16 + r] = ww;
            }
        }
    }
    __syncthreads();

    {
        int i  = tid >> 2;
        int d0 = (tid & 3) * 16;
        float c16[16];
        #pragma unroll
        for (int dd = 0; dd < 16; ++dd) c16[dd] = 0.f;
        const float* srow = sc + i * 64;
        for (int j = 0; j < 64; ++j) {
            float a = srow[j];
            const float* vr = vs + j * LDQ + d0;
            #pragma unroll
            for (int dd = 0; dd < 16; ++dd) c16[dd] = fmaf(a, vr[dd], c16[dd]);
        }
        #pragma unroll
        for (int r = 0; r < NREL; ++r) {
            float wh = Wh[i * 16 + r], ww = Ww[i * 16 + r];
            const float* eh = t_evh + r * LDE + d0;
            const float* ew = t_evw + r * LDE + d0;
            #pragma unroll
            for (int dd = 0; dd < 16; ++dd)
                c16[dd] = fmaf(wh, eh[dd], fmaf(ww, ew[dd], c16[dd]));
        }
        // fp16 write (fused conversion for out-proj input)
        __half hv[16];
        #pragma unroll
        for (int dd = 0; dd < 16; ++dd) hv[dd] = __float2half(c16[dd]);
        int b = bx >> 4, h = bx & 15;
        size_t off = (size_t)(b * SS + i) * DD + h * DH + d0;
        *(uint4*)&g_a[off]     = *(uint4*)&hv[0];
        *(uint4*)&g_a[off + 8] = *(uint4*)&hv[8];
    }
}

// ---------------------------------------------------------------------------
extern "C" void kernel_launch(void* const* d_in, const int* in_sizes, int n_in,
                              void* d_out, int out_size) {
    const float* x    = (const float*)d_in[0];
    const float* wq   = (const float*)d_in[1];
    const float* wk   = (const float*)d_in[2];
    const float* wv   = (const float*)d_in[3];
    const float* wo   = (const float*)d_in[4];
    const float* bo   = (const float*)d_in[5];
    const float* eq_h = (const float*)d_in[6];
    const float* eq_w = (const float*)d_in[7];
    const float* ek_h = (const float*)d_in[8];
    const float* ek_w = (const float*)d_in[9];
    const float* ev_h = (const float*)d_in[10];
    const float* ev_w = (const float*)d_in[11];
    float* out = (float*)d_out;

    cudaFuncSetAttribute(qkv_hmma, cudaFuncAttributeMaxDynamicSharedMemorySize, GEMM_SMEM);
    cudaFuncSetAttribute(out_hmma, cudaFuncAttributeMaxDynamicSharedMemorySize, GEMM_SMEM);
    cudaFuncSetAttribute(attn_kernel, cudaFuncAttributeMaxDynamicSharedMemorySize, ATT_SMEM_BYTES);

    void *p_a = nullptr, *p_wh = nullptr, *p_wl = nullptr;
    cudaGetSymbolAddress(&p_a,  g_a);
    cudaGetSymbolAddress(&p_wh, g_wh);
    cudaGetSymbolAddress(&p_wl, g_wl);
    __half* wh = (__half*)p_wh;
    __half* wl = (__half*)p_wl;

    prep_kernel<<<16, 256>>>(eq_h, eq_w, ek_h, ek_w);
    conv_act_kernel<<<8192, 256>>>(x, (__half*)p_a);
    conv_wsplit_kernel<<<512, 256>>>(wq, wh + (size_t)0*DD*DD, wl + (size_t)0*DD*DD);
    conv_wsplit_kernel<<<512, 256>>>(wk, wh + (size_t)1*DD*DD, wl + (size_t)1*DD*DD);
    conv_wsplit_kernel<<<512, 256>>>(wv, wh + (size_t)2*DD*DD, wl + (size_t)2*DD*DD);
    conv_wsplit_kernel<<<512, 256>>>(wo, wh + (size_t)3*DD*DD, wl + (size_t)3*DD*DD);

    qkv_hmma<<<dim3(24, 128), 512, GEMM_SMEM>>>();
    attn_kernel<<<BB * HH, 256, ATT_SMEM_BYTES>>>(eq_h, eq_w, ek_h, ek_w, ev_h, ev_w);
    out_hmma<<<dim3(8, 128), 512, GEMM_SMEM>>>(bo, out);
}

// round 6
// speedup vs baseline: 3.5674x; 1.4588x over previous
#include <cuda_runtime.h>
#include <cuda_fp16.h>
#include <cstdint>

// Problem constants
#define BB 256
#define SS 64
#define DD 1024
#define HH 16
#define DH 64
#define NREL 15
#define MTOT (BB*SS)   // 16384

// ---------------------------------------------------------------------------
// Device scratch
// ---------------------------------------------------------------------------
__device__ __align__(1024) float g_q[(size_t)BB*HH*SS*DH];
__device__ __align__(1024) float g_k[(size_t)BB*HH*SS*DH];
__device__ __align__(1024) float g_v[(size_t)BB*HH*SS*DH];
__device__ float g_c[SS*SS];

// fp16 buffers: activations and weights, single precision term each
__device__ __align__(1024) __half g_a [(size_t)MTOT*DD];      // x, then ctx (fp16)
__device__ __align__(1024) __half g_wh[(size_t)4*DD*DD];      // weights fp16

// ---------------------------------------------------------------------------
// PTX helpers (arch-baseline: sm_80/75 features only)
// ---------------------------------------------------------------------------
__device__ __forceinline__ uint32_t smem_u32(const void* p) {
    uint32_t a;
    asm("{ .reg .u64 t; cvta.to.shared.u64 t, %1; cvt.u32.u64 %0, t; }" : "=r"(a) : "l"(p));
    return a;
}
__device__ __forceinline__ void cp16(uint32_t dst, const void* src) {
    asm volatile("cp.async.cg.shared.global [%0], [%1], 16;" :: "r"(dst), "l"(src));
}
__device__ __forceinline__ void cp_commit() {
    asm volatile("cp.async.commit_group;" ::: "memory");
}
template<int N> __device__ __forceinline__ void cp_wait() {
    asm volatile("cp.async.wait_group %0;" :: "n"(N) : "memory");
}
__device__ __forceinline__ void ldsm4(uint32_t (&r)[4], uint32_t a) {
    asm volatile("ldmatrix.sync.aligned.m8n8.x4.shared.b16 {%0,%1,%2,%3}, [%4];"
                 : "=r"(r[0]), "=r"(r[1]), "=r"(r[2]), "=r"(r[3]) : "r"(a));
}
__device__ __forceinline__ void mma16816(float (&c)[4], const uint32_t (&a)[4],
                                         uint32_t b0, uint32_t b1) {
    asm volatile("mma.sync.aligned.m16n8k16.row.col.f32.f16.f16.f32 "
                 "{%0,%1,%2,%3}, {%4,%5,%6,%7}, {%8,%9}, {%0,%1,%2,%3};"
                 : "+f"(c[0]), "+f"(c[1]), "+f"(c[2]), "+f"(c[3])
                 : "r"(a[0]), "r"(a[1]), "r"(a[2]), "r"(a[3]), "r"(b0), "r"(b1));
}

// ---------------------------------------------------------------------------
// prep: c[i][j] = (eq_h[rr]+eq_w[rc]) . (ek_h[rr]+ek_w[rc])
// ---------------------------------------------------------------------------
__global__ void prep_kernel(const float* __restrict__ eq_h, const float* __restrict__ eq_w,
                            const float* __restrict__ ek_h, const float* __restrict__ ek_w) {
    int idx = blockIdx.x * 256 + threadIdx.x;
    int i = idx >> 6, j = idx & 63;
    int rr = (i >> 3) - (j >> 3) + 7;
    int rc = (i & 7) - (j & 7) + 7;
    float acc = 0.f;
    #pragma unroll 8
    for (int d = 0; d < 64; ++d) {
        float a = eq_h[rr * 64 + d] + eq_w[rc * 64 + d];
        float b = ek_h[rr * 64 + d] + ek_w[rc * 64 + d];
        acc += a * b;
    }
    g_c[idx] = acc;
}

// ---------------------------------------------------------------------------
// fp32 -> fp16. One thread = 8 elems.
// ---------------------------------------------------------------------------
__global__ __launch_bounds__(256) void conv_act_kernel(
    const float* __restrict__ src, __half* __restrict__ dst) {
    size_t base = ((size_t)blockIdx.x * 256 + threadIdx.x) * 8;
    float4 a = *(const float4*)(src + base);
    float4 b = *(const float4*)(src + base + 4);
    float v[8] = {a.x, a.y, a.z, a.w, b.x, b.y, b.z, b.w};
    __half h[8];
    #pragma unroll
    for (int i = 0; i < 8; ++i) h[i] = __float2half(v[i]);
    *(uint4*)(dst + base) = *(uint4*)h;
}

// ---------------------------------------------------------------------------
// HMMA fp16 GEMM core: acc(128x128) = A(128x1024) * W(128x1024)^T
// 512 threads, 16 warps (4x4), warp tile 32x32. 4-stage ring, 16KB/stage:
//   A @0, B @8192; rows 64B wide, 16B-chunk swizzle ((k8 ^ (row>>1)) & 3).
// ---------------------------------------------------------------------------
#define STAGES 4
#define STAGE_BYTES 16384
#define GEMM_SMEM (STAGES * STAGE_BYTES)

__device__ __forceinline__ void gemm_acc(
    const __half* __restrict__ Ap, const __half* __restrict__ Bp,
    int mbase, int nbase, float acc[2][4][4])
{
    extern __shared__ unsigned char sm_raw[];
    uint32_t smbase = smem_u32(sm_raw);
    int tid = threadIdx.x, lane = tid & 31, wid = tid >> 5;
    int wm = (wid >> 2) * 32, wn = (wid & 3) * 32;

    #pragma unroll
    for (int i = 0; i < 2; ++i)
        #pragma unroll
        for (int j = 0; j < 4; ++j)
            #pragma unroll
            for (int e = 0; e < 4; ++e) acc[i][j][e] = 0.f;

    const __half* srcA = Ap + (size_t)mbase * DD;
    const __half* srcB = Bp + (size_t)nbase * DD;

    int lm  = tid >> 2;            // 0..127
    int lk8 = tid & 3;             // 16B chunk within 64B row
    uint32_t loff = (uint32_t)(lm * 64 + ((lk8 ^ (lm >> 1)) & 3) * 16);

    #define LOAD_CHUNK(kc, st) do {                                            \
        uint32_t sb_ = smbase + (st) * STAGE_BYTES;                            \
        size_t g_ = (size_t)lm * DD + (kc) * 32 + lk8 * 8;                     \
        cp16(sb_ + loff,        srcA + g_);                                    \
        cp16(sb_ + 8192 + loff, srcB + g_);                                    \
        cp_commit();                                                           \
    } while (0)

    LOAD_CHUNK(0, 0);
    LOAD_CHUNK(1, 1);
    LOAD_CHUNK(2, 2);

    int arow = wm + (lane & 7) + ((lane >> 3) & 1) * 8;
    int brow = wn + (lane & 7) + ((lane >> 3) & 1) * 8;
    int k8l  = (lane >> 4);   // 0 or 1; actual k8 = 2*s16 + k8l

    for (int kc = 0; kc < 32; ++kc) {
        cp_wait<2>();
        __syncthreads();
        if (kc + 3 < 32) LOAD_CHUNK(kc + 3, (kc + 3) & 3);
        else             cp_commit();
        uint32_t sb = smbase + (kc & 3) * STAGE_BYTES;

        #pragma unroll
        for (int s16 = 0; s16 < 2; ++s16) {
            int k8 = 2 * s16 + k8l;
            uint32_t av[2][4];
            #pragma unroll
            for (int i = 0; i < 2; ++i) {
                int r = arow + i * 16;
                uint32_t ad = sb + (uint32_t)(r * 64 + ((k8 ^ (r >> 1)) & 3) * 16);
                ldsm4(av[i], ad);
            }
            uint32_t bv[2][4];
            #pragma unroll
            for (int jp = 0; jp < 2; ++jp) {
                int r = brow + jp * 16;
                uint32_t ad = sb + 8192 + (uint32_t)(r * 64 + ((k8 ^ (r >> 1)) & 3) * 16);
                ldsm4(bv[jp], ad);
            }
            #pragma unroll
            for (int i = 0; i < 2; ++i)
                #pragma unroll
                for (int j = 0; j < 4; ++j)
                    mma16816(acc[i][j], av[i],
                             bv[j >> 1][j & 1], bv[j >> 1][(j & 1) + 2]);
        }
    }
    #undef LOAD_CHUNK
}

// ---------------------------------------------------------------------------
// QKV GEMM: grid (24, 128). nt>>3 selects q/k/v, (nt&7)*128 = n0.
// ---------------------------------------------------------------------------
__global__ __launch_bounds__(512, 1) void qkv_hmma() {
    int nt = blockIdx.x, mt = blockIdx.y;
    int which = nt >> 3, nq = nt & 7;
    float acc[2][4][4];
    gemm_acc(g_a, g_wh + (size_t)which * DD * DD, mt * 128, nq * 128, acc);

    float* dst = (which == 0) ? g_q : (which == 1) ? g_k : g_v;
    int lane = threadIdx.x & 31, wid = threadIdx.x >> 5;
    int wm = (wid >> 2) * 32, wn = (wid & 3) * 32;
    int l4 = lane >> 2, l2 = (lane & 3) * 2;

    #pragma unroll
    for (int i = 0; i < 2; ++i)
        #pragma unroll
        for (int j = 0; j < 4; ++j) {
            int m = mt * 128 + wm + i * 16 + l4;
            int n = nq * 128 + wn + j * 8 + l2;
            int h = n >> 6, d = n & 63;
            int b = m >> 6, s = m & 63;
            *(float2*)&dst[(((size_t)(b * HH + h) * SS + s) << 6) + d] =
                make_float2(acc[i][j][0], acc[i][j][1]);
            *(float2*)&dst[(((size_t)(b * HH + h) * SS + (s + 8)) << 6) + d] =
                make_float2(acc[i][j][2], acc[i][j][3]);
        }
}

// ---------------------------------------------------------------------------
// Output GEMM: grid (8, 128). out = ctx @ wo^T + bo
// ---------------------------------------------------------------------------
__global__ __launch_bounds__(512, 1) void out_hmma(const float* __restrict__ bo,
                                                   float* __restrict__ out) {
    int nt = blockIdx.x, mt = blockIdx.y;
    float acc[2][4][4];
    gemm_acc(g_a, g_wh + (size_t)3 * DD * DD, mt * 128, nt * 128, acc);

    int lane = threadIdx.x & 31, wid = threadIdx.x >> 5;
    int wm = (wid >> 2) * 32, wn = (wid & 3) * 32;
    int l4 = lane >> 2, l2 = (lane & 3) * 2;

    #pragma unroll
    for (int i = 0; i < 2; ++i)
        #pragma unroll
        for (int j = 0; j < 4; ++j) {
            int m = mt * 128 + wm + i * 16 + l4;
            int n = nt * 128 + wn + j * 8 + l2;
            float b0 = __ldg(bo + n), b1 = __ldg(bo + n + 1);
            *(float2*)&out[(size_t)m * DD + n] =
                make_float2(acc[i][j][0] + b0, acc[i][j][1] + b1);
            *(float2*)&out[(size_t)(m + 8) * DD + n] =
                make_float2(acc[i][j][2] + b0, acc[i][j][3] + b1);
        }
}

// ---------------------------------------------------------------------------
// Attention: one block per (b,h). smem trimmed to fit 2 CTAs/SM; odd strides
// for conflict-free column access. Epilogue writes fp16 ctx.
// ---------------------------------------------------------------------------
#define LDQ 65
#define LDE 65
#define ATT_SMEM_FLOATS (3*64*LDQ + 4096 + 6*NREL*LDE + 6*1024)
#define ATT_SMEM_BYTES  (ATT_SMEM_FLOATS * 4)   // 114280 <= 114688

__global__ __launch_bounds__(256, 2) void attn_kernel(
    const float* __restrict__ eq_h, const float* __restrict__ eq_w,
    const float* __restrict__ ek_h, const float* __restrict__ ek_w,
    const float* __restrict__ ev_h, const float* __restrict__ ev_w)
{
    extern __shared__ float sm[];
    float* qs    = sm;
    float* ks    = qs + 64 * LDQ;
    float* vs    = ks + 64 * LDQ;
    float* sc    = vs + 64 * LDQ;
    float* t_ekh = sc + 4096;
    float* t_ekw = t_ekh + NREL * LDE;
    float* t_eqh = t_ekw + NREL * LDE;
    float* t_eqw = t_eqh + NREL * LDE;
    float* t_evh = t_eqw + NREL * LDE;
    float* t_evw = t_evh + NREL * LDE;
    float* Ah    = t_evw + NREL * LDE;
    float* Aw    = Ah + 1024;
    float* Ch    = Aw + 1024;
    float* Cw    = Ch + 1024;
    float* Wh    = Cw + 1024;
    float* Ww    = Wh + 1024;

    int tid = threadIdx.x;
    int bx  = blockIdx.x;
    size_t base = (size_t)bx * (SS * DH);

    // Scalar loads (LDQ=65 breaks float4 alignment; volume is small)
    #pragma unroll
    for (int it = 0; it < 16; ++it) {
        int e = it * 256 + tid;
        int s = e >> 6, d = e & 63;
        qs[s * LDQ + d] = g_q[base + e];
        ks[s * LDQ + d] = g_k[base + e];
        vs[s * LDQ + d] = g_v[base + e];
    }
    for (int idx = tid; idx < NREL * 64; idx += 256) {
        int r = idx >> 6, d = idx & 63;
        int o = r * LDE + d;
        t_ekh[o] = ek_h[idx]; t_ekw[o] = ek_w[idx];
        t_eqh[o] = eq_h[idx]; t_eqw[o] = eq_w[idx];
        t_evh[o] = ev_h[idx]; t_evw[o] = ev_w[idx];
    }
    __syncthreads();

    {
        int r = tid & 15, i0 = tid >> 4;
        if (r < NREL) {
            for (int i = i0; i < 64; i += 16) {
                const float* qrow = qs + i * LDQ;
                const float* krow = ks + i * LDQ;
                const float* ekh = t_ekh + r * LDE; const float* ekw = t_ekw + r * LDE;
                const float* eqh = t_eqh + r * LDE; const float* eqw = t_eqw + r * LDE;
                float ah = 0.f, aw = 0.f, ch = 0.f, cw = 0.f;
                #pragma unroll 8
                for (int d = 0; d < 64; ++d) {
                    float qv = qrow[d], kv = krow[d];
                    ah = fmaf(qv, ekh[d], ah);
                    aw = fmaf(qv, ekw[d], aw);
                    ch = fmaf(kv, eqh[d], ch);
                    cw = fmaf(kv, eqw[d], cw);
                }
                Ah[i * 16 + r] = ah; Aw[i * 16 + r] = aw;
                Ch[i * 16 + r] = ch; Cw[i * 16 + r] = cw;
            }
        }
    }
    __syncthreads();

    {
        int ti = tid >> 4, tj = tid & 15;
        float accv[4][4];
        #pragma unroll
        for (int a = 0; a < 4; ++a)
            #pragma unroll
            for (int b = 0; b < 4; ++b) accv[a][b] = 0.f;
        const float* qa = qs + (ti * 4) * LDQ;
        const float* kb = ks + (tj * 4) * LDQ;
        #pragma unroll 4
        for (int d = 0; d < 64; ++d) {
            float a0 = qa[d], a1 = qa[LDQ + d], a2 = qa[2 * LDQ + d], a3 = qa[3 * LDQ + d];
            float b0 = kb[d], b1 = kb[LDQ + d], b2 = kb[2 * LDQ + d], b3 = kb[3 * LDQ + d];
            accv[0][0] = fmaf(a0, b0, accv[0][0]); accv[0][1] = fmaf(a0, b1, accv[0][1]);
            accv[0][2] = fmaf(a0, b2, accv[0][2]); accv[0][3] = fmaf(a0, b3, accv[0][3]);
            accv[1][0] = fmaf(a1, b0, accv[1][0]); accv[1][1] = fmaf(a1, b1, accv[1][1]);
            accv[1][2] = fmaf(a1, b2, accv[1][2]); accv[1][3] = fmaf(a1, b3, accv[1][3]);
            accv[2][0] = fmaf(a2, b0, accv[2][0]); accv[2][1] = fmaf(a2, b1, accv[2][1]);
            accv[2][2] = fmaf(a2, b2, accv[2][2]); accv[2][3] = fmaf(a2, b3, accv[2][3]);
            accv[3][0] = fmaf(a3, b0, accv[3][0]); accv[3][1] = fmaf(a3, b1, accv[3][1]);
            accv[3][2] = fmaf(a3, b2, accv[3][2]); accv[3][3] = fmaf(a3, b3, accv[3][3]);
        }
        #pragma unroll
        for (int ii = 0; ii < 4; ++ii)
            #pragma unroll
            for (int jj = 0; jj < 4; ++jj) {
                int i = ti * 4 + ii, j = tj * 4 + jj;
                int rr = (i >> 3) - (j >> 3) + 7;
                int rc = (i & 7) - (j & 7) + 7;
                float sv = accv[ii][jj] + Ah[i * 16 + rr] + Aw[i * 16 + rc]
                         + Ch[j * 16 + rr] + Cw[j * 16 + rc] + __ldg(&g_c[i * 64 + j]);
                sc[i * 64 + j] = sv * 0.125f;
            }
    }
    __syncthreads();

    {
        int wid = tid >> 5, lane = tid & 31;
        for (int row = wid; row < 64; row += 8) {
            float* srow = sc + row * 64;
            float x0 = srow[lane], x1 = srow[lane + 32];
            float m = fmaxf(x0, x1);
            #pragma unroll
            for (int o = 16; o > 0; o >>= 1) m = fmaxf(m, __shfl_xor_sync(0xffffffffu, m, o));
            float e0 = __expf(x0 - m), e1 = __expf(x1 - m);
            float ssum = e0 + e1;
            #pragma unroll
            for (int o = 16; o > 0; o >>= 1) ssum += __shfl_xor_sync(0xffffffffu, ssum, o);
            float inv = 1.0f / ssum;
            srow[lane] = e0 * inv; srow[lane + 32] = e1 * inv;
        }
    }
    __syncthreads();

    {
        int r = tid & 15, i0 = tid >> 4;
        if (r < NREL) {
            for (int i = i0; i < 64; i += 16) {
                int rowi = i >> 3, coli = i & 7;
                int rowj = rowi - (r - 7);
                float wh = 0.f;
                if (rowj >= 0 && rowj < 8) {
                    const float* p = sc + i * 64 + rowj * 8;
                    #pragma unroll
                    for (int c = 0; c < 8; ++c) wh += p[c];
                }
                int colj = coli - (r - 7);
                float ww = 0.f;
                if (colj >= 0 && colj < 8) {
                    const float* p = sc + i * 64 + colj;
                    #pragma unroll
                    for (int rj = 0; rj < 8; ++rj) ww += p[rj * 8];
                }
                Wh[i * 16 + r] = wh; Ww[i * 16 + r] = ww;
            }
        }
    }
    __syncthreads();

    {
        int i  = tid >> 2;
        int d0 = (tid & 3) * 16;
        float c16[16];
        #pragma unroll
        for (int dd = 0; dd < 16; ++dd) c16[dd] = 0.f;
        const float* srow = sc + i * 64;
        for (int j = 0; j < 64; ++j) {
            float a = srow[j];
            const float* vr = vs + j * LDQ + d0;
            #pragma unroll
            for (int dd = 0; dd < 16; ++dd) c16[dd] = fmaf(a, vr[dd], c16[dd]);
        }
        #pragma unroll
        for (int r = 0; r < NREL; ++r) {
            float wh = Wh[i * 16 + r], ww = Ww[i * 16 + r];
            const float* eh = t_evh + r * LDE + d0;
            const float* ew = t_evw + r * LDE + d0;
            #pragma unroll
            for (int dd = 0; dd < 16; ++dd)
                c16[dd] = fmaf(wh, eh[dd], fmaf(ww, ew[dd], c16[dd]));
        }
        __half hv[16];
        #pragma unroll
        for (int dd = 0; dd < 16; ++dd) hv[dd] = __float2half(c16[dd]);
        int b = bx >> 4, h = bx & 15;
        size_t off = (size_t)(b * SS + i) * DD + h * DH + d0;
        *(uint4*)&g_a[off]     = *(uint4*)&hv[0];
        *(uint4*)&g_a[off + 8] = *(uint4*)&hv[8];
    }
}

// ---------------------------------------------------------------------------
extern "C" void kernel_launch(void* const* d_in, const int* in_sizes, int n_in,
                              void* d_out, int out_size) {
    const float* x    = (const float*)d_in[0];
    const float* wq   = (const float*)d_in[1];
    const float* wk   = (const float*)d_in[2];
    const float* wv   = (const float*)d_in[3];
    const float* wo   = (const float*)d_in[4];
    const float* bo   = (const float*)d_in[5];
    const float* eq_h = (const float*)d_in[6];
    const float* eq_w = (const float*)d_in[7];
    const float* ek_h = (const float*)d_in[8];
    const float* ek_w = (const float*)d_in[9];
    const float* ev_h = (const float*)d_in[10];
    const float* ev_w = (const float*)d_in[11];
    float* out = (float*)d_out;

    cudaFuncSetAttribute(qkv_hmma, cudaFuncAttributeMaxDynamicSharedMemorySize, GEMM_SMEM);
    cudaFuncSetAttribute(out_hmma, cudaFuncAttributeMaxDynamicSharedMemorySize, GEMM_SMEM);
    cudaFuncSetAttribute(attn_kernel, cudaFuncAttributeMaxDynamicSharedMemorySize, ATT_SMEM_BYTES);

    void *p_a = nullptr, *p_wh = nullptr;
    cudaGetSymbolAddress(&p_a,  g_a);
    cudaGetSymbolAddress(&p_wh, g_wh);
    __half* wh = (__half*)p_wh;

    prep_kernel<<<16, 256>>>(eq_h, eq_w, ek_h, ek_w);
    conv_act_kernel<<<8192, 256>>>(x, (__half*)p_a);
    conv_act_kernel<<<512, 256>>>(wq, wh + (size_t)0*DD*DD);
    conv_act_kernel<<<512, 256>>>(wk, wh + (size_t)1*DD*DD);
    conv_act_kernel<<<512, 256>>>(wv, wh + (size_t)2*DD*DD);
    conv_act_kernel<<<512, 256>>>(wo, wh + (size_t)3*DD*DD);

    qkv_hmma<<<dim3(24, 128), 512, GEMM_SMEM>>>();
    attn_kernel<<<BB * HH, 256, ATT_SMEM_BYTES>>>(eq_h, eq_w, ek_h, ek_w, ev_h, ev_w);
    out_hmma<<<dim3(8, 128), 512, GEMM_SMEM>>>(bo, out);
}

// round 7
// speedup vs baseline: 5.7759x; 1.6191x over previous
#include <cuda_runtime.h>
#include <cuda_fp16.h>
#include <cstdint>

// Problem constants
#define BB 256
#define SS 64
#define DD 1024
#define HH 16
#define DH 64
#define NREL 15
#define MTOT (BB*SS)   // 16384

// ---------------------------------------------------------------------------
// Device scratch
// ---------------------------------------------------------------------------
__device__ float g_c[SS*SS];

__device__ __align__(1024) __half g_a [(size_t)MTOT*DD];      // x, then ctx (fp16)
__device__ __align__(1024) __half g_wh[(size_t)4*DD*DD];      // weights fp16

// q/k split hi+lo, v single ; layout (B,H,S,DH) row-major fp16
__device__ __align__(1024) __half g_qh[(size_t)MTOT*DD];
__device__ __align__(1024) __half g_ql[(size_t)MTOT*DD];
__device__ __align__(1024) __half g_kh[(size_t)MTOT*DD];
__device__ __align__(1024) __half g_kl[(size_t)MTOT*DD];
__device__ __align__(1024) __half g_vh[(size_t)MTOT*DD];

// rel tables fp16 (padded to 16 rows x 64)
__device__ __half g_ekh16[1024];
__device__ __half g_ekw16[1024];
__device__ __half g_eqh16[1024];
__device__ __half g_eqw16[1024];
__device__ __half g_evh16[1024];
__device__ __half g_evw16[1024];

// ---------------------------------------------------------------------------
// PTX helpers (arch-baseline: sm_80/75 features only)
// ---------------------------------------------------------------------------
__device__ __forceinline__ uint32_t smem_u32(const void* p) {
    uint32_t a;
    asm("{ .reg .u64 t; cvta.to.shared.u64 t, %1; cvt.u32.u64 %0, t; }" : "=r"(a) : "l"(p));
    return a;
}
__device__ __forceinline__ void cp16(uint32_t dst, const void* src) {
    asm volatile("cp.async.cg.shared.global [%0], [%1], 16;" :: "r"(dst), "l"(src));
}
__device__ __forceinline__ void cp_commit() {
    asm volatile("cp.async.commit_group;" ::: "memory");
}
template<int N> __device__ __forceinline__ void cp_wait() {
    asm volatile("cp.async.wait_group %0;" :: "n"(N) : "memory");
}
__device__ __forceinline__ void ldsm4(uint32_t (&r)[4], uint32_t a) {
    asm volatile("ldmatrix.sync.aligned.m8n8.x4.shared.b16 {%0,%1,%2,%3}, [%4];"
                 : "=r"(r[0]), "=r"(r[1]), "=r"(r[2]), "=r"(r[3]) : "r"(a));
}
__device__ __forceinline__ void mma16816(float (&c)[4], const uint32_t (&a)[4],
                                         uint32_t b0, uint32_t b1) {
    asm volatile("mma.sync.aligned.m16n8k16.row.col.f32.f16.f16.f32 "
                 "{%0,%1,%2,%3}, {%4,%5,%6,%7}, {%8,%9}, {%0,%1,%2,%3};"
                 : "+f"(c[0]), "+f"(c[1]), "+f"(c[2]), "+f"(c[3])
                 : "r"(a[0]), "r"(a[1]), "r"(a[2]), "r"(a[3]), "r"(b0), "r"(b1));
}

// swizzled tile addressing: L128 = rows of 64 halves (8 x 16B chunks),
// L64 = rows of 32 halves (4 x 16B chunks)
__device__ __forceinline__ uint32_t l128(int r, int c) {
    return (uint32_t)(r * 128 + (((c ^ (r & 7)) & 7) << 4));
}
__device__ __forceinline__ uint32_t l64(int r, int c) {
    return (uint32_t)(r * 64 + (((c ^ (r >> 1)) & 3) << 4));
}

// ---------------------------------------------------------------------------
// prep: c[i][j] = (eq_h[rr]+eq_w[rc]) . (ek_h[rr]+ek_w[rc])
// ---------------------------------------------------------------------------
__global__ void prep_kernel(const float* __restrict__ eq_h, const float* __restrict__ eq_w,
                            const float* __restrict__ ek_h, const float* __restrict__ ek_w) {
    int idx = blockIdx.x * 256 + threadIdx.x;
    int i = idx >> 6, j = idx & 63;
    int rr = (i >> 3) - (j >> 3) + 7;
    int rc = (i & 7) - (j & 7) + 7;
    float acc = 0.f;
    #pragma unroll 8
    for (int d = 0; d < 64; ++d) {
        float a = eq_h[rr * 64 + d] + eq_w[rc * 64 + d];
        float b = ek_h[rr * 64 + d] + ek_w[rc * 64 + d];
        acc += a * b;
    }
    g_c[idx] = acc;
}

// fp32 -> fp16, 8 elems/thread
__global__ __launch_bounds__(256) void conv_act_kernel(
    const float* __restrict__ src, __half* __restrict__ dst) {
    size_t base = ((size_t)blockIdx.x * blockDim.x + threadIdx.x) * 8;
    float4 a = *(const float4*)(src + base);
    float4 b = *(const float4*)(src + base + 4);
    float v[8] = {a.x, a.y, a.z, a.w, b.x, b.y, b.z, b.w};
    __half h[8];
    #pragma unroll
    for (int i = 0; i < 8; ++i) h[i] = __float2half(v[i]);
    *(uint4*)(dst + base) = *(uint4*)h;
}

// rel table conv: 960 fp32 -> fp16, pad to 1024 with zeros
__global__ void conv_rel_kernel(const float* __restrict__ src, __half* __restrict__ dst) {
    int t = threadIdx.x;
    dst[t] = (t < 960) ? __float2half(src[t]) : __float2half(0.f);
}

// ---------------------------------------------------------------------------
// HMMA fp16 GEMM core (same as R6): acc(128x128) = A * W^T, K=1024
// ---------------------------------------------------------------------------
#define STAGES 4
#define STAGE_BYTES 16384
#define GEMM_SMEM (STAGES * STAGE_BYTES)

__device__ __forceinline__ void gemm_acc(
    const __half* __restrict__ Ap, const __half* __restrict__ Bp,
    int mbase, int nbase, float acc[2][4][4])
{
    extern __shared__ unsigned char sm_raw[];
    uint32_t smbase = smem_u32(sm_raw);
    int tid = threadIdx.x, lane = tid & 31, wid = tid >> 5;
    int wm = (wid >> 2) * 32, wn = (wid & 3) * 32;

    #pragma unroll
    for (int i = 0; i < 2; ++i)
        #pragma unroll
        for (int j = 0; j < 4; ++j)
            #pragma unroll
            for (int e = 0; e < 4; ++e) acc[i][j][e] = 0.f;

    const __half* srcA = Ap + (size_t)mbase * DD;
    const __half* srcB = Bp + (size_t)nbase * DD;

    int lm  = tid >> 2;
    int lk8 = tid & 3;
    uint32_t loff = (uint32_t)(lm * 64 + ((lk8 ^ (lm >> 1)) & 3) * 16);

    #define LOAD_CHUNK(kc, st) do {                                            \
        uint32_t sb_ = smbase + (st) * STAGE_BYTES;                            \
        size_t g_ = (size_t)lm * DD + (kc) * 32 + lk8 * 8;                     \
        cp16(sb_ + loff,        srcA + g_);                                    \
        cp16(sb_ + 8192 + loff, srcB + g_);                                    \
        cp_commit();                                                           \
    } while (0)

    LOAD_CHUNK(0, 0);
    LOAD_CHUNK(1, 1);
    LOAD_CHUNK(2, 2);

    int arow = wm + (lane & 7) + ((lane >> 3) & 1) * 8;
    int brow = wn + (lane & 7) + ((lane >> 3) & 1) * 8;
    int k8l  = (lane >> 4);

    for (int kc = 0; kc < 32; ++kc) {
        cp_wait<2>();
        __syncthreads();
        if (kc + 3 < 32) LOAD_CHUNK(kc + 3, (kc + 3) & 3);
        else             cp_commit();
        uint32_t sb = smbase + (kc & 3) * STAGE_BYTES;

        #pragma unroll
        for (int s16 = 0; s16 < 2; ++s16) {
            int k8 = 2 * s16 + k8l;
            uint32_t av[2][4];
            #pragma unroll
            for (int i = 0; i < 2; ++i) {
                int r = arow + i * 16;
                uint32_t ad = sb + (uint32_t)(r * 64 + ((k8 ^ (r >> 1)) & 3) * 16);
                ldsm4(av[i], ad);
            }
            uint32_t bv[2][4];
            #pragma unroll
            for (int jp = 0; jp < 2; ++jp) {
                int r = brow + jp * 16;
                uint32_t ad = sb + 8192 + (uint32_t)(r * 64 + ((k8 ^ (r >> 1)) & 3) * 16);
                ldsm4(bv[jp], ad);
            }
            #pragma unroll
            for (int i = 0; i < 2; ++i)
                #pragma unroll
                for (int j = 0; j < 4; ++j)
                    mma16816(acc[i][j], av[i],
                             bv[j >> 1][j & 1], bv[j >> 1][(j & 1) + 2]);
        }
    }
    #undef LOAD_CHUNK
}

// ---------------------------------------------------------------------------
// QKV GEMM: epilogue writes fp16 q/k (hi+lo) and v into (B,H,S,DH)
// ---------------------------------------------------------------------------
__global__ __launch_bounds__(512, 1) void qkv_hmma() {
    int nt = blockIdx.x, mt = blockIdx.y;
    int which = nt >> 3, nq = nt & 7;
    float acc[2][4][4];
    gemm_acc(g_a, g_wh + (size_t)which * DD * DD, mt * 128, nq * 128, acc);

    __half* dh = (which == 0) ? g_qh : (which == 1) ? g_kh : g_vh;
    __half* dl = (which == 0) ? g_ql : g_kl;
    int lane = threadIdx.x & 31, wid = threadIdx.x >> 5;
    int wm = (wid >> 2) * 32, wn = (wid & 3) * 32;
    int l4 = lane >> 2, l2 = (lane & 3) * 2;

    #pragma unroll
    for (int i = 0; i < 2; ++i)
        #pragma unroll
        for (int j = 0; j < 4; ++j) {
            int m = mt * 128 + wm + i * 16 + l4;
            int n = nq * 128 + wn + j * 8 + l2;
            int h = n >> 6, d = n & 63;
            int b = m >> 6, s = m & 63;
            size_t i0 = ((size_t)((b * HH + h) * SS + s)) * 64 + d;
            size_t i1 = ((size_t)((b * HH + h) * SS + s + 8)) * 64 + d;
            float v0 = acc[i][j][0], v1 = acc[i][j][1];
            float v2 = acc[i][j][2], v3 = acc[i][j][3];
            __half h0 = __float2half(v0), h1 = __float2half(v1);
            __half h2 = __float2half(v2), h3 = __float2half(v3);
            *(__half2*)(dh + i0) = __halves2half2(h0, h1);
            *(__half2*)(dh + i1) = __halves2half2(h2, h3);
            if (which < 2) {
                __half l0 = __float2half(v0 - __half2float(h0));
                __half l1 = __float2half(v1 - __half2float(h1));
                __half l2h = __float2half(v2 - __half2float(h2));
                __half l3 = __float2half(v3 - __half2float(h3));
                *(__half2*)(dl + i0) = __halves2half2(l0, l1);
                *(__half2*)(dl + i1) = __halves2half2(l2h, l3);
            }
        }
}

// ---------------------------------------------------------------------------
// Output GEMM: out = ctx @ wo^T + bo
// ---------------------------------------------------------------------------
__global__ __launch_bounds__(512, 1) void out_hmma(const float* __restrict__ bo,
                                                   float* __restrict__ out) {
    int nt = blockIdx.x, mt = blockIdx.y;
    float acc[2][4][4];
    gemm_acc(g_a, g_wh + (size_t)3 * DD * DD, mt * 128, nt * 128, acc);

    int lane = threadIdx.x & 31, wid = threadIdx.x >> 5;
    int wm = (wid >> 2) * 32, wn = (wid & 3) * 32;
    int l4 = lane >> 2, l2 = (lane & 3) * 2;

    #pragma unroll
    for (int i = 0; i < 2; ++i)
        #pragma unroll
        for (int j = 0; j < 4; ++j) {
            int m = mt * 128 + wm + i * 16 + l4;
            int n = nt * 128 + wn + j * 8 + l2;
            float b0 = __ldg(bo + n), b1 = __ldg(bo + n + 1);
            *(float2*)&out[(size_t)m * DD + n] =
                make_float2(acc[i][j][0] + b0, acc[i][j][1] + b1);
            *(float2*)&out[(size_t)(m + 8) * DD + n] =
                make_float2(acc[i][j][2] + b0, acc[i][j][3] + b1);
        }
}

// ---------------------------------------------------------------------------
// MMA attention: one head per CTA (256 threads, 8 warps). grid = 4096.
// smem map (bytes):
//   Qh@0 Kh@8192 VT@16384 WW@24576 EC@28672 EK@32768(4x2048)
//   T@40960 (Ah,Aw,Ch,Cw fp32 64x18 each=4608)  [P@40960, PL@49152 overlay]
//   QL@59392 KL@67584                            [S fp32 64x65 @59392 overlay]
// ---------------------------------------------------------------------------
#define AT_Q   0
#define AT_K   8192
#define AT_VT  16384
#define AT_WW  24576
#define AT_EC  28672
#define AT_EK  32768
#define AT_T   40960
#define AT_P   40960
#define AT_PL  49152
#define AT_QL  59392
#define AT_KL  67584
#define AT_S   59392
#define AT_BYTES 84480   // 67584 + 16384 (KL) ... (covers S overlay at 59392+16640)

__global__ __launch_bounds__(256, 2) void attn_mma() {
    extern __shared__ unsigned char am_raw[];
    uint32_t sb = smem_u32(am_raw);
    float* sSf = (float*)(am_raw + AT_S);     // stride 65
    int tid = threadIdx.x, lane = tid & 31, w = tid >> 5;
    int bx = blockIdx.x;
    int b = bx >> 4, h = bx & 15;
    size_t gbase = (size_t)bx * 4096;

    // ---- load Qh/Ql/Kh/Kl via cp.async into L128 swizzled tiles ----
    #pragma unroll
    for (int it = 0; it < 2; ++it) {
        int e = it * 256 + tid;
        int r = e >> 3, c = e & 7;
        uint32_t off = l128(r, c);
        size_t g = gbase + r * 64 + c * 8;
        cp16(sb + AT_Q  + off, g_qh + g);
        cp16(sb + AT_QL + off, g_ql + g);
        cp16(sb + AT_K  + off, g_kh + g);
        cp16(sb + AT_KL + off, g_kl + g);
    }
    cp_commit();

    // ---- VT[d][j] = v[j][d] (scalar transpose) ----
    #pragma unroll
    for (int it = 0; it < 8; ++it) {
        int e = it * 256 + tid;
        int j = e >> 5, dp = e & 31;
        uint32_t wv = *(const uint32_t*)(g_vh + gbase + j * 64 + dp * 2);
        int d0 = dp * 2, d1 = d0 + 1;
        *(unsigned short*)(am_raw + AT_VT + l128(d0, j >> 3) + (j & 7) * 2) = (unsigned short)(wv & 0xffff);
        *(unsigned short*)(am_raw + AT_VT + l128(d1, j >> 3) + (j & 7) * 2) = (unsigned short)(wv >> 16);
    }
    // ---- EK tables: ekh,ekw,eqh,eqw as [16][64] L128 ----
    #pragma unroll
    for (int it = 0; it < 16; ++it) {
        int e = it * 256 + tid;
        int t = e >> 10, r = (e >> 6) & 15, d = e & 63;
        const __half* src = (t == 0) ? g_ekh16 : (t == 1) ? g_ekw16 : (t == 2) ? g_eqh16 : g_eqw16;
        __half v = src[r * 64 + d];   // rows >=15 pre-zeroed in conv
        *(unsigned short*)(am_raw + AT_EK + t * 2048 + l128(r, d >> 3) + (d & 7) * 2) = *(unsigned short*)&v;
    }
    // ---- EC: [d][r] combined [evh | evw] 64x32 L64 ----
    #pragma unroll
    for (int it = 0; it < 8; ++it) {
        int e = it * 256 + tid;
        int d = e >> 5, c = e & 31;
        __half v = __float2half(0.f);
        if (c < 15)            v = g_evh16[c * 64 + d];
        else if (c >= 16 && c < 31) v = g_evw16[(c - 16) * 64 + d];
        *(unsigned short*)(am_raw + AT_EC + l64(d, c >> 3) + (c & 7) * 2) = *(unsigned short*)&v;
    }
    cp_wait<0>();
    __syncthreads();

    // ---- Phase 1: S (3-term split) + table mmas ----
    int ms = (w & 3) * 16, ns = (w >> 2) * 32;
    float s[4][4];
    float t0[2][4], t1[2][4];
    #pragma unroll
    for (int j = 0; j < 4; ++j) {
        #pragma unroll
        for (int e = 0; e < 4; ++e) s[j][e] = 0.f;
        if (j < 2) { t0[j][0]=t0[j][1]=t0[j][2]=t0[j][3]=0.f; t1[j][0]=t1[j][1]=t1[j][2]=t1[j][3]=0.f; }
    }
    int lrow = (lane & 7) + ((lane >> 3) & 1) * 8;
    int lc   = lane >> 4;
    #pragma unroll
    for (int kk = 0; kk < 4; ++kk) {
        int c = 2 * kk + lc;
        uint32_t ah[4], al[4];
        {
            uint32_t off = l128(ms + lrow, c);
            ldsm4(ah, sb + AT_Q  + off);
            ldsm4(al, sb + AT_QL + off);
        }
        uint32_t bh[2][4], bl[2][4];
        #pragma unroll
        for (int jp = 0; jp < 2; ++jp) {
            uint32_t off = l128(ns + jp * 16 + lrow, c);
            ldsm4(bh[jp], sb + AT_K  + off);
            ldsm4(bl[jp], sb + AT_KL + off);
        }
        #pragma unroll
        for (int j = 0; j < 4; ++j) {
            uint32_t b0h = bh[j >> 1][j & 1], b1h = bh[j >> 1][(j & 1) + 2];
            uint32_t b0l = bl[j >> 1][j & 1], b1l = bl[j >> 1][(j & 1) + 2];
            mma16816(s[j], ah, b0h, b1h);
            mma16816(s[j], ah, b0l, b1l);
            mma16816(s[j], al, b0h, b1h);
        }
        // tables: warps 0-3 Q x {ekh,ekw}; warps 4-7 K x {eqh,eqw}
        uint32_t ta[4];
        if (w < 4) { ta[0]=ah[0]; ta[1]=ah[1]; ta[2]=ah[2]; ta[3]=ah[3]; }
        else       ldsm4(ta, sb + AT_K + l128(ms + lrow, c));
        uint32_t e0[4], e1[4];
        {
            uint32_t off = l128(lrow, c);
            int tb = (w < 4) ? 0 : 2;
            ldsm4(e0, sb + AT_EK + tb * 2048 + off);
            ldsm4(e1, sb + AT_EK + (tb + 1) * 2048 + off);
        }
        #pragma unroll
        for (int jc = 0; jc < 2; ++jc) {
            mma16816(t0[jc], ta, e0[jc], e0[jc + 2]);
            mma16816(t1[jc], ta, e1[jc], e1[jc + 2]);
        }
    }
    // store table frags (fp32, stride 18)
    {
        int l4 = lane >> 2, l2 = lane & 3;
        unsigned char* tb0 = am_raw + AT_T + ((w < 4) ? 0 : 2 * 4608);
        #pragma unroll
        for (int jc = 0; jc < 2; ++jc) {
            int r0 = jc * 8 + l2 * 2;
            int i0 = ms + l4;
            *(float2*)(tb0 + (size_t)(i0 * 18 + r0) * 4)        = make_float2(t0[jc][0], t0[jc][1]);
            *(float2*)(tb0 + (size_t)((i0 + 8) * 18 + r0) * 4)  = make_float2(t0[jc][2], t0[jc][3]);
            *(float2*)(tb0 + 4608 + (size_t)(i0 * 18 + r0) * 4)       = make_float2(t1[jc][0], t1[jc][1]);
            *(float2*)(tb0 + 4608 + (size_t)((i0 + 8) * 18 + r0) * 4) = make_float2(t1[jc][2], t1[jc][3]);
        }
    }
    __syncthreads();

    // ---- bias + write logits to sS (stride 65) ----
    {
        int l4 = lane >> 2, l2 = lane & 3;
        const float* Ah = (const float*)(am_raw + AT_T);
        const float* Aw = Ah + 64 * 18;
        const float* Ch = Aw + 64 * 18;
        const float* Cw = Ch + 64 * 18;
        #pragma unroll
        for (int jc = 0; jc < 4; ++jc)
            #pragma unroll
            for (int q = 0; q < 2; ++q)
                #pragma unroll
                for (int p = 0; p < 2; ++p) {
                    int i = ms + l4 + q * 8;
                    int j = ns + jc * 8 + l2 * 2 + p;
                    int rr = (i >> 3) - (j >> 3) + 7;
                    int rc = (i & 7) - (j & 7) + 7;
                    float v = s[jc][q * 2 + p]
                            + Ah[i * 18 + rr] + Aw[i * 18 + rc]
                            + Ch[j * 18 + rr] + Cw[j * 18 + rc]
                            + __ldg(&g_c[i * 64 + j]);
                    sSf[i * 65 + j] = v * 0.125f;
                }
    }
    __syncthreads();

    // ---- softmax + split-fp16 P write ----
    for (int row = w; row < 64; row += 8) {
        float* sr = sSf + row * 65;
        float x0 = sr[lane], x1 = sr[lane + 32];
        float m = fmaxf(x0, x1);
        #pragma unroll
        for (int o = 16; o > 0; o >>= 1) m = fmaxf(m, __shfl_xor_sync(0xffffffffu, m, o));
        float e0 = __expf(x0 - m), e1 = __expf(x1 - m);
        float ssum = e0 + e1;
        #pragma unroll
        for (int o = 16; o > 0; o >>= 1) ssum += __shfl_xor_sync(0xffffffffu, ssum, o);
        float inv = 1.0f / ssum;
        float p0 = e0 * inv, p1 = e1 * inv;
        sr[lane] = p0; sr[lane + 32] = p1;
        __half h0 = __float2half(p0);
        __half l0 = __float2half(p0 - __half2float(h0));
        __half h1 = __float2half(p1);
        __half l1 = __float2half(p1 - __half2float(h1));
        int c0 = lane, c1 = lane + 32;
        *(unsigned short*)(am_raw + AT_P  + l128(row, c0 >> 3) + (c0 & 7) * 2) = *(unsigned short*)&h0;
        *(unsigned short*)(am_raw + AT_P  + l128(row, c1 >> 3) + (c1 & 7) * 2) = *(unsigned short*)&h1;
        *(unsigned short*)(am_raw + AT_PL + l128(row, c0 >> 3) + (c0 & 7) * 2) = *(unsigned short*)&l0;
        *(unsigned short*)(am_raw + AT_PL + l128(row, c1 >> 3) + (c1 & 7) * 2) = *(unsigned short*)&l1;
    }
    __syncthreads();

    // ---- Wh/Ww masked row sums -> WW tile (fp16, L64) ----
    {
        int r = tid & 15, i0 = tid >> 4;
        for (int i = i0; i < 64; i += 16) {
            float wh = 0.f, ww = 0.f;
            if (r < 15) {
                int rowi = i >> 3, coli = i & 7;
                int rowj = rowi - (r - 7);
                if (rowj >= 0 && rowj < 8) {
                    const float* p = sSf + i * 65 + rowj * 8;
                    #pragma unroll
                    for (int cc = 0; cc < 8; ++cc) wh += p[cc];
                }
                int colj = coli - (r - 7);
                if (colj >= 0 && colj < 8) {
                    const float* p = sSf + i * 65 + colj;
                    #pragma unroll
                    for (int rj = 0; rj < 8; ++rj) ww += p[rj * 8];
                }
            }
            __half hwh = __float2half(wh), hww = __float2half(ww);
            int cw = r + 16;
            *(unsigned short*)(am_raw + AT_WW + l64(i, r >> 3)  + (r  & 7) * 2) = *(unsigned short*)&hwh;
            *(unsigned short*)(am_raw + AT_WW + l64(i, cw >> 3) + (cw & 7) * 2) = *(unsigned short*)&hww;
        }
    }
    __syncthreads();

    // ---- ctx: P·V^T (2-term) + WW·EC ----
    {
        float o[4][4];
        #pragma unroll
        for (int j = 0; j < 4; ++j) { o[j][0]=o[j][1]=o[j][2]=o[j][3]=0.f; }
        #pragma unroll
        for (int kk = 0; kk < 4; ++kk) {
            int c = 2 * kk + lc;
            uint32_t ph[4], pl[4];
            {
                uint32_t off = l128(ms + lrow, c);
                ldsm4(ph, sb + AT_P  + off);
                ldsm4(pl, sb + AT_PL + off);
            }
            uint32_t bv[2][4];
            #pragma unroll
            for (int jp = 0; jp < 2; ++jp)
                ldsm4(bv[jp], sb + AT_VT + l128(ns + jp * 16 + lrow, c));
            #pragma unroll
            for (int j = 0; j < 4; ++j) {
                uint32_t b0 = bv[j >> 1][j & 1], b1 = bv[j >> 1][(j & 1) + 2];
                mma16816(o[j], ph, b0, b1);
                mma16816(o[j], pl, b0, b1);
            }
        }
        #pragma unroll
        for (int kk = 0; kk < 2; ++kk) {
            int c = 2 * kk + lc;
            uint32_t aw_[4];
            {
                int r = ms + lrow;
                ldsm4(aw_, sb + AT_WW + (uint32_t)(r * 64 + (((c ^ (r >> 1)) & 3) << 4)));
            }
            uint32_t ev[2][4];
            #pragma unroll
            for (int jp = 0; jp < 2; ++jp) {
                int r = ns + jp * 16 + lrow;
                ldsm4(ev[jp], sb + AT_EC + (uint32_t)(r * 64 + (((c ^ (r >> 1)) & 3) << 4)));
            }
            #pragma unroll
            for (int j = 0; j < 4; ++j)
                mma16816(o[j], aw_, ev[j >> 1][j & 1], ev[j >> 1][(j & 1) + 2]);
        }
        // epilogue: fp16 ctx into g_a (B,S,D)
        int l4 = lane >> 2, l2 = lane & 3;
        #pragma unroll
        for (int jc = 0; jc < 4; ++jc) {
            int d = ns + jc * 8 + l2 * 2;
            int i = ms + l4;
            *(__half2*)(g_a + (size_t)(b * 64 + i) * DD + h * 64 + d) =
                __halves2half2(__float2half(o[jc][0]), __float2half(o[jc][1]));
            *(__half2*)(g_a + (size_t)(b * 64 + i + 8) * DD + h * 64 + d) =
                __halves2half2(__float2half(o[jc][2]), __float2half(o[jc][3]));
        }
    }
}

// ---------------------------------------------------------------------------
extern "C" void kernel_launch(void* const* d_in, const int* in_sizes, int n_in,
                              void* d_out, int out_size) {
    const float* x    = (const float*)d_in[0];
    const float* wq   = (const float*)d_in[1];
    const float* wk   = (const float*)d_in[2];
    const float* wv   = (const float*)d_in[3];
    const float* wo   = (const float*)d_in[4];
    const float* bo   = (const float*)d_in[5];
    const float* eq_h = (const float*)d_in[6];
    const float* eq_w = (const float*)d_in[7];
    const float* ek_h = (const float*)d_in[8];
    const float* ek_w = (const float*)d_in[9];
    const float* ev_h = (const float*)d_in[10];
    const float* ev_w = (const float*)d_in[11];
    float* out = (float*)d_out;

    cudaFuncSetAttribute(qkv_hmma, cudaFuncAttributeMaxDynamicSharedMemorySize, GEMM_SMEM);
    cudaFuncSetAttribute(out_hmma, cudaFuncAttributeMaxDynamicSharedMemorySize, GEMM_SMEM);
    cudaFuncSetAttribute(attn_mma, cudaFuncAttributeMaxDynamicSharedMemorySize, AT_BYTES);

    void *p_a = nullptr, *p_wh = nullptr;
    void *p_eqh = nullptr, *p_eqw = nullptr, *p_ekh = nullptr, *p_ekw = nullptr;
    void *p_evh = nullptr, *p_evw = nullptr;
    cudaGetSymbolAddress(&p_a,  g_a);
    cudaGetSymbolAddress(&p_wh, g_wh);
    cudaGetSymbolAddress(&p_eqh, g_eqh16);
    cudaGetSymbolAddress(&p_eqw, g_eqw16);
    cudaGetSymbolAddress(&p_ekh, g_ekh16);
    cudaGetSymbolAddress(&p_ekw, g_ekw16);
    cudaGetSymbolAddress(&p_evh, g_evh16);
    cudaGetSymbolAddress(&p_evw, g_evw16);
    __half* wh = (__half*)p_wh;

    prep_kernel<<<16, 256>>>(eq_h, eq_w, ek_h, ek_w);
    conv_act_kernel<<<8192, 256>>>(x, (__half*)p_a);
    conv_act_kernel<<<512, 256>>>(wq, wh + (size_t)0*DD*DD);
    conv_act_kernel<<<512, 256>>>(wk, wh + (size_t)1*DD*DD);
    conv_act_kernel<<<512, 256>>>(wv, wh + (size_t)2*DD*DD);
    conv_act_kernel<<<512, 256>>>(wo, wh + (size_t)3*DD*DD);
    conv_rel_kernel<<<1, 1024>>>(eq_h, (__half*)p_eqh);
    conv_rel_kernel<<<1, 1024>>>(eq_w, (__half*)p_eqw);
    conv_rel_kernel<<<1, 1024>>>(ek_h, (__half*)p_ekh);
    conv_rel_kernel<<<1, 1024>>>(ek_w, (__half*)p_ekw);
    conv_rel_kernel<<<1, 1024>>>(ev_h, (__half*)p_evh);
    conv_rel_kernel<<<1, 1024>>>(ev_w, (__half*)p_evw);

    qkv_hmma<<<dim3(24, 128), 512, GEMM_SMEM>>>();
    attn_mma<<<BB * HH, 256, AT_BYTES>>>();
    out_hmma<<<dim3(8, 128), 512, GEMM_SMEM>>>(bo, out);
}

// round 8
// speedup vs baseline: 6.6827x; 1.1570x over previous
#include <cuda_runtime.h>
#include <cuda_fp16.h>
#include <cstdint>

// Problem constants
#define BB 256
#define SS 64
#define DD 1024
#define HH 16
#define DH 64
#define NREL 15
#define MTOT (BB*SS)   // 16384

// ---------------------------------------------------------------------------
// Device scratch
// ---------------------------------------------------------------------------
__device__ float g_c[SS*SS];

__device__ __align__(1024) __half g_a [(size_t)MTOT*DD];      // x, then ctx (fp16)
__device__ __align__(1024) __half g_wh[(size_t)4*DD*DD];      // weights fp16

// q/k split hi+lo, v single ; layout (B,H,S,DH) row-major fp16
__device__ __align__(1024) __half g_qh[(size_t)MTOT*DD];
__device__ __align__(1024) __half g_ql[(size_t)MTOT*DD];
__device__ __align__(1024) __half g_kh[(size_t)MTOT*DD];
__device__ __align__(1024) __half g_kl[(size_t)MTOT*DD];
__device__ __align__(1024) __half g_vh[(size_t)MTOT*DD];

// pre-swizzled fp16 table tiles (final smem layout; cp.async straight in)
__device__ __align__(16) __half g_ektiles[4096];   // 4 tables x 16rows x 64 (L128)
__device__ __align__(16) __half g_ectile[2048];    // [evh|pad|evw|pad] 32 x 64 (L128)

// ---------------------------------------------------------------------------
// PTX helpers (arch-baseline: sm_80/75 features only)
// ---------------------------------------------------------------------------
__device__ __forceinline__ uint32_t smem_u32(const void* p) {
    uint32_t a;
    asm("{ .reg .u64 t; cvta.to.shared.u64 t, %1; cvt.u32.u64 %0, t; }" : "=r"(a) : "l"(p));
    return a;
}
__device__ __forceinline__ void cp16(uint32_t dst, const void* src) {
    asm volatile("cp.async.cg.shared.global [%0], [%1], 16;" :: "r"(dst), "l"(src));
}
__device__ __forceinline__ void cp_commit() {
    asm volatile("cp.async.commit_group;" ::: "memory");
}
template<int N> __device__ __forceinline__ void cp_wait() {
    asm volatile("cp.async.wait_group %0;" :: "n"(N) : "memory");
}
__device__ __forceinline__ void ldsm4(uint32_t (&r)[4], uint32_t a) {
    asm volatile("ldmatrix.sync.aligned.m8n8.x4.shared.b16 {%0,%1,%2,%3}, [%4];"
                 : "=r"(r[0]), "=r"(r[1]), "=r"(r[2]), "=r"(r[3]) : "r"(a));
}
__device__ __forceinline__ void ldsm4t(uint32_t (&r)[4], uint32_t a) {
    asm volatile("ldmatrix.sync.aligned.m8n8.x4.trans.shared.b16 {%0,%1,%2,%3}, [%4];"
                 : "=r"(r[0]), "=r"(r[1]), "=r"(r[2]), "=r"(r[3]) : "r"(a));
}
__device__ __forceinline__ void mma16816(float (&c)[4], const uint32_t (&a)[4],
                                         uint32_t b0, uint32_t b1) {
    asm volatile("mma.sync.aligned.m16n8k16.row.col.f32.f16.f16.f32 "
                 "{%0,%1,%2,%3}, {%4,%5,%6,%7}, {%8,%9}, {%0,%1,%2,%3};"
                 : "+f"(c[0]), "+f"(c[1]), "+f"(c[2]), "+f"(c[3])
                 : "r"(a[0]), "r"(a[1]), "r"(a[2]), "r"(a[3]), "r"(b0), "r"(b1));
}

__device__ __forceinline__ uint32_t l128(int r, int c) {
    return (uint32_t)(r * 128 + (((c ^ (r & 7)) & 7) << 4));
}
__device__ __forceinline__ uint32_t l64(int r, int c) {
    return (uint32_t)(r * 64 + (((c ^ (r >> 1)) & 3) << 4));
}

// ---------------------------------------------------------------------------
// prep: c[i][j] = (eq_h[rr]+eq_w[rc]) . (ek_h[rr]+ek_w[rc])
// ---------------------------------------------------------------------------
__global__ void prep_kernel(const float* __restrict__ eq_h, const float* __restrict__ eq_w,
                            const float* __restrict__ ek_h, const float* __restrict__ ek_w) {
    int idx = blockIdx.x * 256 + threadIdx.x;
    int i = idx >> 6, j = idx & 63;
    int rr = (i >> 3) - (j >> 3) + 7;
    int rc = (i & 7) - (j & 7) + 7;
    float acc = 0.f;
    #pragma unroll 8
    for (int d = 0; d < 64; ++d) {
        float a = eq_h[rr * 64 + d] + eq_w[rc * 64 + d];
        float b = ek_h[rr * 64 + d] + ek_w[rc * 64 + d];
        acc += a * b;
    }
    g_c[idx] = acc;
}

// Build EK/EC swizzled fp16 tiles. grid 6 x 1024.
__global__ void prep_tiles(const float* __restrict__ ek_h, const float* __restrict__ ek_w,
                           const float* __restrict__ eq_h, const float* __restrict__ eq_w,
                           const float* __restrict__ ev_h, const float* __restrict__ ev_w) {
    int idx = blockIdx.x * 1024 + threadIdx.x;
    if (idx < 4096) {
        int t = idx >> 10, r = (idx >> 6) & 15, d = idx & 63;
        const float* src = (t == 0) ? ek_h : (t == 1) ? ek_w : (t == 2) ? eq_h : eq_w;
        __half v = __float2half((r < 15) ? src[r * 64 + d] : 0.f);
        *(unsigned short*)((char*)g_ektiles + t * 2048 + l128(r, d >> 3) + (d & 7) * 2) =
            *(unsigned short*)&v;
    } else {
        int e = idx - 4096;
        int r = e >> 6, d = e & 63;
        float f = 0.f;
        if (r < 15) f = ev_h[r * 64 + d];
        else if (r >= 16 && r < 31) f = ev_w[(r - 16) * 64 + d];
        __half v = __float2half(f);
        *(unsigned short*)((char*)g_ectile + l128(r, d >> 3) + (d & 7) * 2) =
            *(unsigned short*)&v;
    }
}

// fp32 -> fp16, 16 elems/thread
__global__ __launch_bounds__(256) void conv_act_kernel(
    const float* __restrict__ src, __half* __restrict__ dst) {
    size_t base = ((size_t)blockIdx.x * 256 + threadIdx.x) * 16;
    #pragma unroll
    for (int half8 = 0; half8 < 2; ++half8) {
        size_t bb = base + half8 * 8;
        float4 a = *(const float4*)(src + bb);
        float4 c = *(const float4*)(src + bb + 4);
        float v[8] = {a.x, a.y, a.z, a.w, c.x, c.y, c.z, c.w};
        __half h[8];
        #pragma unroll
        for (int i = 0; i < 8; ++i) h[i] = __float2half(v[i]);
        *(uint4*)(dst + bb) = *(uint4*)h;
    }
}

// 4 weights -> fp16 in one launch. grid 2048 x 256, 8 elems/thread.
__global__ __launch_bounds__(256) void conv_w4(
    const float* __restrict__ w0, const float* __restrict__ w1,
    const float* __restrict__ w2, const float* __restrict__ w3,
    __half* __restrict__ dst) {
    int blk = blockIdx.x;
    int which = blk >> 9;
    const float* src = (which == 0) ? w0 : (which == 1) ? w1 : (which == 2) ? w2 : w3;
    size_t lbase = ((size_t)(blk & 511) * 256 + threadIdx.x) * 8;
    float4 a = *(const float4*)(src + lbase);
    float4 c = *(const float4*)(src + lbase + 4);
    float v[8] = {a.x, a.y, a.z, a.w, c.x, c.y, c.z, c.w};
    __half h[8];
    #pragma unroll
    for (int i = 0; i < 8; ++i) h[i] = __float2half(v[i]);
    *(uint4*)(dst + (size_t)which * DD * DD + lbase) = *(uint4*)h;
}

// ---------------------------------------------------------------------------
// HMMA fp16 GEMM core (validated): acc(128x128) = A * W^T, K=1024
// ---------------------------------------------------------------------------
#define STAGES 4
#define STAGE_BYTES 16384
#define GEMM_SMEM (STAGES * STAGE_BYTES)

__device__ __forceinline__ void gemm_acc(
    const __half* __restrict__ Ap, const __half* __restrict__ Bp,
    int mbase, int nbase, float acc[2][4][4])
{
    extern __shared__ unsigned char sm_raw[];
    uint32_t smbase = smem_u32(sm_raw);
    int tid = threadIdx.x, lane = tid & 31, wid = tid >> 5;
    int wm = (wid >> 2) * 32, wn = (wid & 3) * 32;

    #pragma unroll
    for (int i = 0; i < 2; ++i)
        #pragma unroll
        for (int j = 0; j < 4; ++j)
            #pragma unroll
            for (int e = 0; e < 4; ++e) acc[i][j][e] = 0.f;

    const __half* srcA = Ap + (size_t)mbase * DD;
    const __half* srcB = Bp + (size_t)nbase * DD;

    int lm  = tid >> 2;
    int lk8 = tid & 3;
    uint32_t loff = (uint32_t)(lm * 64 + ((lk8 ^ (lm >> 1)) & 3) * 16);

    #define LOAD_CHUNK(kc, st) do {                                            \
        uint32_t sb_ = smbase + (st) * STAGE_BYTES;                            \
        size_t g_ = (size_t)lm * DD + (kc) * 32 + lk8 * 8;                     \
        cp16(sb_ + loff,        srcA + g_);                                    \
        cp16(sb_ + 8192 + loff, srcB + g_);                                    \
        cp_commit();                                                           \
    } while (0)

    LOAD_CHUNK(0, 0);
    LOAD_CHUNK(1, 1);
    LOAD_CHUNK(2, 2);

    int arow = wm + (lane & 7) + ((lane >> 3) & 1) * 8;
    int brow = wn + (lane & 7) + ((lane >> 3) & 1) * 8;
    int k8l  = (lane >> 4);

    for (int kc = 0; kc < 32; ++kc) {
        cp_wait<2>();
        __syncthreads();
        if (kc + 3 < 32) LOAD_CHUNK(kc + 3, (kc + 3) & 3);
        else             cp_commit();
        uint32_t sb = smbase + (kc & 3) * STAGE_BYTES;

        #pragma unroll
        for (int s16 = 0; s16 < 2; ++s16) {
            int k8 = 2 * s16 + k8l;
            uint32_t av[2][4];
            #pragma unroll
            for (int i = 0; i < 2; ++i) {
                int r = arow + i * 16;
                uint32_t ad = sb + (uint32_t)(r * 64 + ((k8 ^ (r >> 1)) & 3) * 16);
                ldsm4(av[i], ad);
            }
            uint32_t bv[2][4];
            #pragma unroll
            for (int jp = 0; jp < 2; ++jp) {
                int r = brow + jp * 16;
                uint32_t ad = sb + 8192 + (uint32_t)(r * 64 + ((k8 ^ (r >> 1)) & 3) * 16);
                ldsm4(bv[jp], ad);
            }
            #pragma unroll
            for (int i = 0; i < 2; ++i)
                #pragma unroll
                for (int j = 0; j < 4; ++j)
                    mma16816(acc[i][j], av[i],
                             bv[j >> 1][j & 1], bv[j >> 1][(j & 1) + 2]);
        }
    }
    #undef LOAD_CHUNK
}

// ---------------------------------------------------------------------------
// QKV GEMM: epilogue writes fp16 q/k (hi+lo) and v into (B,H,S,DH)
// ---------------------------------------------------------------------------
__global__ __launch_bounds__(512, 1) void qkv_hmma() {
    int nt = blockIdx.x, mt = blockIdx.y;
    int which = nt >> 3, nq = nt & 7;
    float acc[2][4][4];
    gemm_acc(g_a, g_wh + (size_t)which * DD * DD, mt * 128, nq * 128, acc);

    __half* dh = (which == 0) ? g_qh : (which == 1) ? g_kh : g_vh;
    __half* dl = (which == 0) ? g_ql : g_kl;
    int lane = threadIdx.x & 31, wid = threadIdx.x >> 5;
    int wm = (wid >> 2) * 32, wn = (wid & 3) * 32;
    int l4 = lane >> 2, l2 = (lane & 3) * 2;

    #pragma unroll
    for (int i = 0; i < 2; ++i)
        #pragma unroll
        for (int j = 0; j < 4; ++j) {
            int m = mt * 128 + wm + i * 16 + l4;
            int n = nq * 128 + wn + j * 8 + l2;
            int h = n >> 6, d = n & 63;
            int b = m >> 6, s = m & 63;
            size_t i0 = ((size_t)((b * HH + h) * SS + s)) * 64 + d;
            size_t i1 = ((size_t)((b * HH + h) * SS + s + 8)) * 64 + d;
            float v0 = acc[i][j][0], v1 = acc[i][j][1];
            float v2 = acc[i][j][2], v3 = acc[i][j][3];
            __half h0 = __float2half(v0), h1 = __float2half(v1);
            __half h2v = __float2half(v2), h3 = __float2half(v3);
            *(__half2*)(dh + i0) = __halves2half2(h0, h1);
            *(__half2*)(dh + i1) = __halves2half2(h2v, h3);
            if (which < 2) {
                __half l0 = __float2half(v0 - __half2float(h0));
                __half l1 = __float2half(v1 - __half2float(h1));
                __half l2h = __float2half(v2 - __half2float(h2v));
                __half l3 = __float2half(v3 - __half2float(h3));
                *(__half2*)(dl + i0) = __halves2half2(l0, l1);
                *(__half2*)(dl + i1) = __halves2half2(l2h, l3);
            }
        }
}

// ---------------------------------------------------------------------------
// Output GEMM: out = ctx @ wo^T + bo
// ---------------------------------------------------------------------------
__global__ __launch_bounds__(512, 1) void out_hmma(const float* __restrict__ bo,
                                                   float* __restrict__ out) {
    int nt = blockIdx.x, mt = blockIdx.y;
    float acc[2][4][4];
    gemm_acc(g_a, g_wh + (size_t)3 * DD * DD, mt * 128, nt * 128, acc);

    int lane = threadIdx.x & 31, wid = threadIdx.x >> 5;
    int wm = (wid >> 2) * 32, wn = (wid & 3) * 32;
    int l4 = lane >> 2, l2 = (lane & 3) * 2;

    #pragma unroll
    for (int i = 0; i < 2; ++i)
        #pragma unroll
        for (int j = 0; j < 4; ++j) {
            int m = mt * 128 + wm + i * 16 + l4;
            int n = nt * 128 + wn + j * 8 + l2;
            float b0 = __ldg(bo + n), b1 = __ldg(bo + n + 1);
            *(float2*)&out[(size_t)m * DD + n] =
                make_float2(acc[i][j][0] + b0, acc[i][j][1] + b1);
            *(float2*)&out[(size_t)(m + 8) * DD + n] =
                make_float2(acc[i][j][2] + b0, acc[i][j][3] + b1);
        }
}

// ---------------------------------------------------------------------------
// MMA attention v2: one head per CTA (256 threads). All operand tiles land
// via cp.async; V/EC consumed with ldmatrix.trans; softmax in registers.
// ---------------------------------------------------------------------------
#define AT_Q   0
#define AT_K   8192
#define AT_QL  16384
#define AT_KL  24576
#define AT_V   32768
#define AT_EK  40960
#define AT_EC  49152
#define AT_WW  53248
#define AT_T   57344
#define AT_P   75776
#define AT_PL  83968
#define AT_PM  92160
#define AT_PS  92672
#define AT_BYTES 93184

__global__ __launch_bounds__(256, 2) void attn_mma() {
    extern __shared__ unsigned char am_raw[];
    uint32_t sb = smem_u32(am_raw);
    int tid = threadIdx.x, lane = tid & 31, w = tid >> 5;
    int bx = blockIdx.x;
    int b = bx >> 4, h = bx & 15;
    size_t gbase = (size_t)bx * 4096;

    // ---- async load everything ----
    #pragma unroll
    for (int it = 0; it < 2; ++it) {
        int e = it * 256 + tid;
        int r = e >> 3, c = e & 7;
        uint32_t off = l128(r, c);
        size_t g = gbase + r * 64 + c * 8;
        cp16(sb + AT_Q  + off, g_qh + g);
        cp16(sb + AT_QL + off, g_ql + g);
        cp16(sb + AT_K  + off, g_kh + g);
        cp16(sb + AT_KL + off, g_kl + g);
        cp16(sb + AT_V  + off, g_vh + g);
        cp16(sb + AT_EK + e * 16, (const char*)g_ektiles + e * 16);
        if (it == 0)
            cp16(sb + AT_EC + tid * 16, (const char*)g_ectile + tid * 16);
    }
    cp_commit();
    cp_wait<0>();
    __syncthreads();

    int ms = (w & 3) * 16, ns = (w >> 2) * 32;
    int lrow = (lane & 7) + ((lane >> 3) & 1) * 8;
    int lc   = lane >> 4;
    int l4 = lane >> 2, l2 = lane & 3;

    // ---- Phase 1: S (3-term split) + table mmas ----
    float s[4][4];
    float t0[2][4], t1[2][4];
    #pragma unroll
    for (int j = 0; j < 4; ++j) {
        s[j][0]=s[j][1]=s[j][2]=s[j][3]=0.f;
        if (j < 2) { t0[j][0]=t0[j][1]=t0[j][2]=t0[j][3]=0.f;
                     t1[j][0]=t1[j][1]=t1[j][2]=t1[j][3]=0.f; }
    }
    #pragma unroll
    for (int kk = 0; kk < 4; ++kk) {
        int c = 2 * kk + lc;
        uint32_t ah[4], al[4];
        uint32_t offq = l128(ms + lrow, c);
        ldsm4(ah, sb + AT_Q  + offq);
        ldsm4(al, sb + AT_QL + offq);
        uint32_t bh[2][4], bl[2][4];
        #pragma unroll
        for (int jp = 0; jp < 2; ++jp) {
            uint32_t off = l128(ns + jp * 16 + lrow, c);
            ldsm4(bh[jp], sb + AT_K  + off);
            ldsm4(bl[jp], sb + AT_KL + off);
        }
        #pragma unroll
        for (int j = 0; j < 4; ++j) {
            uint32_t b0h = bh[j >> 1][j & 1], b1h = bh[j >> 1][(j & 1) + 2];
            uint32_t b0l = bl[j >> 1][j & 1], b1l = bl[j >> 1][(j & 1) + 2];
            mma16816(s[j], ah, b0h, b1h);
            mma16816(s[j], ah, b0l, b1l);
            mma16816(s[j], al, b0h, b1h);
        }
        uint32_t ta[4];
        if (w < 4) { ta[0]=ah[0]; ta[1]=ah[1]; ta[2]=ah[2]; ta[3]=ah[3]; }
        else       ldsm4(ta, sb + AT_K + offq);
        uint32_t e0[4], e1[4];
        int tb = (w < 4) ? 0 : 2;
        uint32_t offe = l128(lrow, c);
        ldsm4(e0, sb + AT_EK + tb * 2048 + offe);
        ldsm4(e1, sb + AT_EK + (tb + 1) * 2048 + offe);
        #pragma unroll
        for (int jc = 0; jc < 2; ++jc) {
            mma16816(t0[jc], ta, e0[jc], e0[jc + 2]);
            mma16816(t1[jc], ta, e1[jc], e1[jc + 2]);
        }
    }
    // store table frags (fp32 stride 18)
    {
        unsigned char* tb0 = am_raw + AT_T + ((w < 4) ? 0 : 2 * 4608);
        #pragma unroll
        for (int jc = 0; jc < 2; ++jc) {
            int r0 = jc * 8 + l2 * 2;
            int i0 = ms + l4;
            *(float2*)(tb0 + (size_t)(i0 * 18 + r0) * 4)        = make_float2(t0[jc][0], t0[jc][1]);
            *(float2*)(tb0 + (size_t)((i0 + 8) * 18 + r0) * 4)  = make_float2(t0[jc][2], t0[jc][3]);
            *(float2*)(tb0 + 4608 + (size_t)(i0 * 18 + r0) * 4)       = make_float2(t1[jc][0], t1[jc][1]);
            *(float2*)(tb0 + 4608 + (size_t)((i0 + 8) * 18 + r0) * 4) = make_float2(t1[jc][2], t1[jc][3]);
        }
    }
    __syncthreads();

    // ---- bias in registers ----
    {
        const float* Ah = (const float*)(am_raw + AT_T);
        const float* Aw = Ah + 1152;
        const float* Ch = Aw + 1152;
        const float* Cw = Ch + 1152;
        #pragma unroll
        for (int jc = 0; jc < 4; ++jc)
            #pragma unroll
            for (int q = 0; q < 2; ++q)
                #pragma unroll
                for (int p = 0; p < 2; ++p) {
                    int i = ms + l4 + q * 8;
                    int j = ns + jc * 8 + l2 * 2 + p;
                    int rr = (i >> 3) - (j >> 3) + 7;
                    int rc = (i & 7) - (j & 7) + 7;
                    s[jc][q * 2 + p] = (s[jc][q * 2 + p]
                        + Ah[i * 18 + rr] + Aw[i * 18 + rc]
                        + Ch[j * 18 + rr] + Cw[j * 18 + rc]
                        + __ldg(&g_c[i * 64 + j])) * 0.125f;
                }
    }

    // ---- register softmax ----
    float* pm = (float*)(am_raw + AT_PM);
    float* ps = (float*)(am_raw + AT_PS);
    {
        float m0 = -1e30f, m1 = -1e30f;
        #pragma unroll
        for (int jc = 0; jc < 4; ++jc) {
            m0 = fmaxf(m0, fmaxf(s[jc][0], s[jc][1]));
            m1 = fmaxf(m1, fmaxf(s[jc][2], s[jc][3]));
        }
        m0 = fmaxf(m0, __shfl_xor_sync(0xffffffffu, m0, 1));
        m0 = fmaxf(m0, __shfl_xor_sync(0xffffffffu, m0, 2));
        m1 = fmaxf(m1, __shfl_xor_sync(0xffffffffu, m1, 1));
        m1 = fmaxf(m1, __shfl_xor_sync(0xffffffffu, m1, 2));
        if (l2 == 0) {
            pm[(w >> 2) * 64 + ms + l4]     = m0;
            pm[(w >> 2) * 64 + ms + l4 + 8] = m1;
        }
    }
    __syncthreads();
    float M0 = fmaxf(pm[ms + l4],     pm[64 + ms + l4]);
    float M1 = fmaxf(pm[ms + l4 + 8], pm[64 + ms + l4 + 8]);
    {
        float s0 = 0.f, s1 = 0.f;
        #pragma unroll
        for (int jc = 0; jc < 4; ++jc) {
            s[jc][0] = __expf(s[jc][0] - M0);
            s[jc][1] = __expf(s[jc][1] - M0);
            s[jc][2] = __expf(s[jc][2] - M1);
            s[jc][3] = __expf(s[jc][3] - M1);
            s0 += s[jc][0] + s[jc][1];
            s1 += s[jc][2] + s[jc][3];
        }
        s0 += __shfl_xor_sync(0xffffffffu, s0, 1);
        s0 += __shfl_xor_sync(0xffffffffu, s0, 2);
        s1 += __shfl_xor_sync(0xffffffffu, s1, 1);
        s1 += __shfl_xor_sync(0xffffffffu, s1, 2);
        if (l2 == 0) {
            ps[(w >> 2) * 64 + ms + l4]     = s0;
            ps[(w >> 2) * 64 + ms + l4 + 8] = s1;
        }
    }
    __syncthreads();
    {
        float inv0 = 1.0f / (ps[ms + l4]     + ps[64 + ms + l4]);
        float inv1 = 1.0f / (ps[ms + l4 + 8] + ps[64 + ms + l4 + 8]);
        #pragma unroll
        for (int jc = 0; jc < 4; ++jc)
            #pragma unroll
            for (int q = 0; q < 2; ++q) {
                int row = ms + l4 + q * 8;
                int j0  = ns + jc * 8 + l2 * 2;
                float inv = q ? inv1 : inv0;
                float p0 = s[jc][q * 2] * inv, p1 = s[jc][q * 2 + 1] * inv;
                __half h0 = __float2half(p0), h1 = __float2half(p1);
                __half lo0 = __float2half(p0 - __half2float(h0));
                __half lo1 = __float2half(p1 - __half2float(h1));
                uint32_t off = l128(row, j0 >> 3) + (j0 & 7) * 2;
                *(__half2*)(am_raw + AT_P  + off) = __halves2half2(h0, h1);
                *(__half2*)(am_raw + AT_PL + off) = __halves2half2(lo0, lo1);
            }
    }
    __syncthreads();

    // ---- Wh/Ww masked row sums -> WW tile ----
    {
        int r = tid & 15, it0 = tid >> 4;
        for (int i = it0; i < 64; i += 16) {
            float wh = 0.f, ww = 0.f;
            if (r < 15) {
                int rowj = (i >> 3) - (r - 7);
                if (rowj >= 0 && rowj < 8) {
                    const __half* hp = (const __half*)(am_raw + AT_P  + l128(i, rowj));
                    const __half* lp = (const __half*)(am_raw + AT_PL + l128(i, rowj));
                    #pragma unroll
                    for (int t = 0; t < 8; ++t)
                        wh += __half2float(hp[t]) + __half2float(lp[t]);
                }
                int colj = (i & 7) - (r - 7);
                if (colj >= 0 && colj < 8) {
                    #pragma unroll
                    for (int rj = 0; rj < 8; ++rj) {
                        ww += __half2float(*(const __half*)(am_raw + AT_P  + l128(i, rj) + colj * 2))
                            + __half2float(*(const __half*)(am_raw + AT_PL + l128(i, rj) + colj * 2));
                    }
                }
            }
            __half hwh = __float2half(wh), hww = __float2half(ww);
            int cw = r + 16;
            *(unsigned short*)(am_raw + AT_WW + l64(i, r >> 3)  + (r  & 7) * 2) = *(unsigned short*)&hwh;
            *(unsigned short*)(am_raw + AT_WW + l64(i, cw >> 3) + (cw & 7) * 2) = *(unsigned short*)&hww;
        }
    }
    __syncthreads();

    // ---- ctx: P·V (trans-B) + WW·EC (trans-B) ----
    {
        float o[4][4];
        #pragma unroll
        for (int j = 0; j < 4; ++j) { o[j][0]=o[j][1]=o[j][2]=o[j][3]=0.f; }
        int trow = (lane & 7) + ((lane >> 3) & 1) * 8;
        int tsel = lane >> 4;

        #pragma unroll
        for (int kk = 0; kk < 4; ++kk) {
            int c = 2 * kk + lc;
            uint32_t ph[4], pl[4];
            uint32_t offp = l128(ms + lrow, c);
            ldsm4(ph, sb + AT_P  + offp);
            ldsm4(pl, sb + AT_PL + offp);
            #pragma unroll
            for (int jp = 0; jp < 2; ++jp) {
                uint32_t bv[4];
                ldsm4t(bv, sb + AT_V + l128(kk * 16 + trow, (ns >> 3) + jp * 2 + tsel));
                mma16816(o[jp * 2],     ph, bv[0], bv[1]);
                mma16816(o[jp * 2],     pl, bv[0], bv[1]);
                mma16816(o[jp * 2 + 1], ph, bv[2], bv[3]);
                mma16816(o[jp * 2 + 1], pl, bv[2], bv[3]);
            }
        }
        #pragma unroll
        for (int kk2 = 0; kk2 < 2; ++kk2) {
            uint32_t aw_[4];
            ldsm4(aw_, sb + AT_WW + l64(ms + lrow, 2 * kk2 + lc));
            #pragma unroll
            for (int jp = 0; jp < 2; ++jp) {
                uint32_t ev[4];
                ldsm4t(ev, sb + AT_EC + l128(kk2 * 16 + trow, (ns >> 3) + jp * 2 + tsel));
                mma16816(o[jp * 2],     aw_, ev[0], ev[1]);
                mma16816(o[jp * 2 + 1], aw_, ev[2], ev[3]);
            }
        }
        #pragma unroll
        for (int jc = 0; jc < 4; ++jc) {
            int d = ns + jc * 8 + l2 * 2;
            int i = ms + l4;
            *(__half2*)(g_a + (size_t)(b * 64 + i) * DD + h * 64 + d) =
                __halves2half2(__float2half(o[jc][0]), __float2half(o[jc][1]));
            *(__half2*)(g_a + (size_t)(b * 64 + i + 8) * DD + h * 64 + d) =
                __halves2half2(__float2half(o[jc][2]), __float2half(o[jc][3]));
        }
    }
}

// ---------------------------------------------------------------------------
extern "C" void kernel_launch(void* const* d_in, const int* in_sizes, int n_in,
                              void* d_out, int out_size) {
    const float* x    = (const float*)d_in[0];
    const float* wq   = (const float*)d_in[1];
    const float* wk   = (const float*)d_in[2];
    const float* wv   = (const float*)d_in[3];
    const float* wo   = (const float*)d_in[4];
    const float* bo   = (const float*)d_in[5];
    const float* eq_h = (const float*)d_in[6];
    const float* eq_w = (const float*)d_in[7];
    const float* ek_h = (const float*)d_in[8];
    const float* ek_w = (const float*)d_in[9];
    const float* ev_h = (const float*)d_in[10];
    const float* ev_w = (const float*)d_in[11];
    float* out = (float*)d_out;

    cudaFuncSetAttribute(qkv_hmma, cudaFuncAttributeMaxDynamicSharedMemorySize, GEMM_SMEM);
    cudaFuncSetAttribute(out_hmma, cudaFuncAttributeMaxDynamicSharedMemorySize, GEMM_SMEM);
    cudaFuncSetAttribute(attn_mma, cudaFuncAttributeMaxDynamicSharedMemorySize, AT_BYTES);

    void *p_a = nullptr, *p_wh = nullptr;
    cudaGetSymbolAddress(&p_a,  g_a);
    cudaGetSymbolAddress(&p_wh, g_wh);

    prep_kernel<<<16, 256>>>(eq_h, eq_w, ek_h, ek_w);
    prep_tiles<<<6, 1024>>>(ek_h, ek_w, eq_h, eq_w, ev_h, ev_w);
    conv_act_kernel<<<4096, 256>>>(x, (__half*)p_a);
    conv_w4<<<2048, 256>>>(wq, wk, wv, wo, (__half*)p_wh);

    qkv_hmma<<<dim3(24, 128), 512, GEMM_SMEM>>>();
    attn_mma<<<BB * HH, 256, AT_BYTES>>>();
    out_hmma<<<dim3(8, 128), 512, GEMM_SMEM>>>(bo, out);
}